// round 8
// baseline (speedup 1.0000x reference)
#include <cuda_runtime.h>
#include <cuda_bf16.h>
#include <cstdint>
#include <math.h>

typedef __nv_bfloat16 bf16;

// Problem constants
#define BB 4
#define TT 512
#define DD 1024
#define HH 8
#define DH 64
#define HD 512
#define PP 2048
#define NTOK (BB*TT)          // 2048 tokens

// ================= scratch (device globals) =================================
__device__ bf16  g_xn_h[NTOK*DD], g_xn_l[NTOK*DD];
__device__ float g_xt  [NTOK*PP];
__device__ bf16  g_xt_h[NTOK*PP], g_xt_l[NTOK*PP];
__device__ float g_xc  [NTOK*PP];
__device__ bf16  g_xc_h[NTOK*PP], g_xc_l[NTOK*PP];
__device__ float g_r   [NTOK*HD], g_skip[NTOK*HD];
__device__ float g_q   [NTOK*HD], g_k   [NTOK*HD];
__device__ float g_v   [NTOK*HD], g_o   [NTOK*HD];
__device__ float g_gates[NTOK*128];      // raw i/f gate pre-activations (cols 0-15)
__device__ float g_a   [BB*HH*TT], g_M [BB*HH*TT];
__device__ bf16  g_cm_h[NTOK*HD], g_cm_l[NTOK*HD];
// transposed + split weights
__device__ bf16 g_WlrT_h[2560*DD], g_WlrT_l[2560*DD];   // [Wl | Wr] cols, K=1024
__device__ bf16 g_WsT_h[HD*PP], g_WsT_l[HD*PP];
__device__ bf16 g_WqT_h[HD*PP], g_WqT_l[HD*PP];
__device__ bf16 g_WkT_h[HD*PP], g_WkT_l[HD*PP];
__device__ bf16 g_WvT_h[HD*PP], g_WvT_l[HD*PP];
__device__ bf16 g_WoT_h[HD*PP], g_WoT_l[HD*PP];
__device__ bf16 g_WdT_h[DD*HD], g_WdT_l[DD*HD];
__device__ bf16 g_WgT_h[128*PP], g_WgT_l[128*PP];       // rows 0-7 Wi, 8-15 Wf, rest 0
__device__ float g_bias_lr[2560];
__device__ float g_bias_g[128];

__device__ __forceinline__ void split_store(float v, bf16* ph, bf16* pl, size_t i) {
    bf16 h = __float2bfloat16(v);
    ph[i] = h;
    pl[i] = __float2bfloat16(v - __bfloat162float(h));
}

__device__ __forceinline__ uint32_t smem_u32(const void* p) {
    uint32_t a;
    asm("{ .reg .u64 t; cvta.to.shared.u64 t, %1; cvt.u32.u64 %0, t; }"
        : "=r"(a) : "l"(p));
    return a;
}
__device__ __forceinline__ void cp16(uint32_t s, const void* g) {
    asm volatile("cp.async.cg.shared.global [%0], [%1], 16;" :: "r"(s), "l"(g));
}
__device__ __forceinline__ void ldm4(uint32_t addr, uint32_t* r) {
    asm volatile("ldmatrix.sync.aligned.m8n8.x4.shared.b16 {%0,%1,%2,%3}, [%4];"
                 : "=r"(r[0]), "=r"(r[1]), "=r"(r[2]), "=r"(r[3]) : "r"(addr));
}
__device__ __forceinline__ void mma16816(float* c, const uint32_t* a,
                                         uint32_t b0, uint32_t b1) {
    asm volatile("mma.sync.aligned.m16n8k16.row.col.f32.bf16.bf16.f32 "
        "{%0,%1,%2,%3}, {%4,%5,%6,%7}, {%8,%9}, {%0,%1,%2,%3};"
        : "+f"(c[0]), "+f"(c[1]), "+f"(c[2]), "+f"(c[3])
        : "r"(a[0]), "r"(a[1]), "r"(a[2]), "r"(a[3]), "r"(b0), "r"(b1));
}

// ================= merged weight transpose + split =========================
struct PrepJobs {
    const float* W[8];
    bf16 *Th[8], *Tl[8];
    int K[8], N[8], cum[9];
};
__global__ __launch_bounds__(256) void prep_all_kernel(PrepJobs pj)
{
    int bx = blockIdx.x, j = 0;
    #pragma unroll
    for (int i = 0; i < 8; i++) if (bx >= pj.cum[i + 1]) j = i + 1;
    const int local = bx - pj.cum[j];
    const int K = pj.K[j], N = pj.N[j];
    const int nbn = N / 32;
    const int n0 = (local % nbn) * 32, k0 = (local / nbn) * 32;
    const float* W = pj.W[j];
    bf16 *Th = pj.Th[j], *Tl = pj.Tl[j];

    __shared__ float tile[32][33];
    int tx = threadIdx.x & 31, ty = threadIdx.x >> 5;
    for (int r = ty; r < 32; r += 8)
        tile[r][tx] = W[(size_t)(k0 + r) * N + n0 + tx];
    __syncthreads();
    for (int r = ty; r < 32; r += 8) {
        float v = tile[tx][r];
        split_store(v, Th, Tl, (size_t)(n0 + r) * K + k0 + tx);
    }
}

// gate weights (Wi|Wf -> 16 rows of WgT) + packed biases
__global__ __launch_bounds__(256) void misc_prep_kernel(
    const float* __restrict__ Wi, const float* __restrict__ Wf,
    const float* __restrict__ bl, const float* __restrict__ br,
    const float* __restrict__ bi, const float* __restrict__ bfp)
{
    const int blk = blockIdx.x, tid = threadIdx.x;
    if (blk < 128) {                       // WgT: 2048*16 elements
        int idx = blk * 256 + tid;         // 0..32767
        int k = idx >> 4, n = idx & 15;
        float v = (n < 8) ? Wi[k * HH + n] : Wf[k * HH + (n - 8)];
        split_store(v, g_WgT_h, g_WgT_l, (size_t)n * PP + k);
    } else if (blk < 138) {                // bias_lr: 2560
        int idx = (blk - 128) * 256 + tid;
        if (idx < 2560)
            g_bias_lr[idx] = (idx < PP) ? bl[idx] : br[idx - PP];
    } else {                               // bias_g: 128
        if (tid < 128)
            g_bias_g[tid] = (tid < 8) ? bi[tid] : (tid < 16 ? bfp[tid - 8] : 0.f);
    }
}

// ================= layernorm + bf16 split ==================================
__global__ __launch_bounds__(256) void ln_split_kernel(
    const float* __restrict__ x, const float* __restrict__ w,
    const float* __restrict__ b, bf16* __restrict__ oh, bf16* __restrict__ ol)
{
    int t = blockIdx.x;
    const float* row = x + (size_t)t * DD;
    float s = 0.f, s2 = 0.f;
    for (int i = threadIdx.x; i < DD; i += 256) {
        float v = row[i]; s += v; s2 += v * v;
    }
    __shared__ float sh[16];
    int warp = threadIdx.x >> 5, lane = threadIdx.x & 31;
    #pragma unroll
    for (int o = 16; o; o >>= 1) {
        s  += __shfl_xor_sync(0xffffffffu, s,  o);
        s2 += __shfl_xor_sync(0xffffffffu, s2, o);
    }
    if (lane == 0) { sh[warp] = s; sh[8 + warp] = s2; }
    __syncthreads();
    if (threadIdx.x == 0) {
        float ts = 0.f, ts2 = 0.f;
        #pragma unroll
        for (int i = 0; i < 8; i++) { ts += sh[i]; ts2 += sh[8 + i]; }
        float mu  = ts  * (1.f / DD);
        float var = ts2 * (1.f / DD) - mu * mu;
        sh[0] = mu; sh[1] = rsqrtf(var + 1e-6f);
    }
    __syncthreads();
    float mu = sh[0], rstd = sh[1];
    for (int i = threadIdx.x; i < DD; i += 256) {
        float y = (row[i] - mu) * rstd * w[i] + b[i];
        split_store(y, oh, ol, (size_t)t * DD + i);
    }
}

// ================= mma.sync split-bf16 GEMM (BK=64) ========================
struct GemmJob {
    const bf16 *Ah, *Al, *Bh, *Bl;
    const float *bias, *res;
    float *out;
    bf16 *oh, *ol;
    float *out2;                  // columns >= ncut go here (ld = ldo2)
    int ncut, ldo, ldo2, nlimit;  // nlimit: skip CTAs with bn >= nlimit
};
struct GemmParams { GemmJob jobs[6]; int K; };

#define PADK 72                        // halves per smem row (64 + 8 pad)
#define OPT  (128*PADK)                // halves per operand tile
#define STG4 (4*OPT)                   // halves per stage (Ah,Al,Bh,Bl)
#define GSMEM_BYTES (2*STG4*2)         // 147456 B

__global__ __launch_bounds__(256, 1) void gemm_mma_kernel(GemmParams p)
{
    const GemmJob J = p.jobs[blockIdx.z];
    const int bm = blockIdx.y * 128, bn = blockIdx.x * 128;
    if (bn >= J.nlimit) return;

    extern __shared__ bf16 smg[];
    const uint32_t sbase = smem_u32(smg);
    const int K = p.K;
    const int tid = threadIdx.x, lane = tid & 31, wid = tid >> 5;
    const int warpM = wid & 3, warpN = wid >> 2;    // 4 x 2 warps, tile 32x64

    const bf16* gsrc[4];
    gsrc[0] = J.Ah + (size_t)bm * K;
    gsrc[1] = J.Al + (size_t)bm * K;
    gsrc[2] = J.Bh + (size_t)bn * K;
    gsrc[3] = J.Bl + (size_t)bn * K;

    // loader: 2 threads per row, 32 halves (64B) each = 4 cp16
    const int lrow = tid >> 1;
    const int lcol = (tid & 1) * 32;   // halves
    const uint32_t swr = sbase + (uint32_t)(lrow * PADK + lcol) * 2;

    float acc[2][8][4];
    #pragma unroll
    for (int i = 0; i < 2; i++)
        #pragma unroll
        for (int j = 0; j < 8; j++)
            #pragma unroll
            for (int e = 0; e < 4; e++) acc[i][j][e] = 0.f;

    const int NT = K / 64;
    {
        #pragma unroll
        for (int w = 0; w < 4; w++) {
            const bf16* g = gsrc[w] + (size_t)lrow * K + lcol;
            uint32_t s = swr + (uint32_t)(w * OPT) * 2;
            cp16(s, g); cp16(s + 16, g + 8); cp16(s + 32, g + 16); cp16(s + 48, g + 24);
        }
        asm volatile("cp.async.commit_group;");
    }

    int buf = 0;
    for (int kt = 0; kt < NT; kt++) {
        if (kt + 1 < NT) {
            const int k0 = (kt + 1) * 64;
            #pragma unroll
            for (int w = 0; w < 4; w++) {
                const bf16* g = gsrc[w] + (size_t)lrow * K + k0 + lcol;
                uint32_t s = swr + (uint32_t)((buf ^ 1) * STG4 + w * OPT) * 2;
                cp16(s, g); cp16(s + 16, g + 8); cp16(s + 32, g + 16); cp16(s + 48, g + 24);
            }
            asm volatile("cp.async.commit_group;");
            asm volatile("cp.async.wait_group 1;");
        } else {
            asm volatile("cp.async.wait_group 0;");
        }
        __syncthreads();

        const uint32_t stg = sbase + (uint32_t)(buf * STG4) * 2;
        #pragma unroll
        for (int ks = 0; ks < 4; ks++) {
            const int koff = ks * 16 + ((lane >> 4) << 3);
            const int rsel = lane & 15;
            uint32_t a[2][2][4], b[2][4][4];
            #pragma unroll
            for (int op = 0; op < 2; op++)
                #pragma unroll
                for (int i = 0; i < 2; i++) {
                    const int row = warpM * 32 + i * 16 + rsel;
                    ldm4(stg + (uint32_t)(op * OPT + row * PADK + koff) * 2,
                         a[op][i]);
                }
            #pragma unroll
            for (int op = 0; op < 2; op++)
                #pragma unroll
                for (int j = 0; j < 4; j++) {
                    const int row = warpN * 64 + j * 16 + rsel;
                    ldm4(stg + (uint32_t)((2 + op) * OPT + row * PADK + koff) * 2,
                         b[op][j]);
                }
            #pragma unroll
            for (int ps = 0; ps < 3; ps++) {
                const int aop = (ps == 2) ? 1 : 0;
                const int bop = (ps == 1) ? 1 : 0;
                #pragma unroll
                for (int i = 0; i < 2; i++)
                    #pragma unroll
                    for (int j = 0; j < 8; j++)
                        mma16816(acc[i][j], a[aop][i],
                                 b[bop][j >> 1][j & 1],
                                 b[bop][j >> 1][(j & 1) + 2]);
            }
        }
        __syncthreads();
        buf ^= 1;
    }

    const int er = (lane >> 2);
    const int ec = (lane & 3) * 2;
    #pragma unroll
    for (int i = 0; i < 2; i++) {
        #pragma unroll
        for (int j = 0; j < 8; j++) {
            const int row0 = bm + warpM * 32 + i * 16 + er;
            const int col0 = bn + warpN * 64 + j * 8 + ec;
            #pragma unroll
            for (int e = 0; e < 4; e++) {
                const int row = row0 + (e >> 1) * 8;
                const int col = col0 + (e & 1);
                float v = acc[i][j][e] + J.bias[col];
                if (col >= J.ncut) {
                    J.out2[(size_t)row * J.ldo2 + (col - J.ncut)] = v;
                } else {
                    if (J.res) v += J.res[(size_t)row * J.ldo + col];
                    const size_t idx = (size_t)row * J.ldo + col;
                    J.out[idx] = v;
                    if (J.oh) split_store(v, J.oh, J.ol, idx);
                }
            }
        }
    }
}

// ================= causal feature-conv + silu + split ======================
__global__ __launch_bounds__(256) void conv_silu_kernel(
    const float* __restrict__ xt, const float* __restrict__ cw,
    const float* __restrict__ cbp, float* __restrict__ xc,
    bf16* __restrict__ xch, bf16* __restrict__ xcl)
{
    int t = blockIdx.x;
    int pcol = blockIdx.y * 256 + threadIdx.x;
    const float* row = xt + (size_t)t * PP;
    float w0 = cw[0], w1 = cw[1], w2 = cw[2], w3 = cw[3];
    float acc = row[pcol] * w3;
    if (pcol >= 1) acc += row[pcol - 1] * w2;
    if (pcol >= 2) acc += row[pcol - 2] * w1;
    if (pcol >= 3) acc += row[pcol - 3] * w0;
    acc += cbp[0];
    float y = acc / (1.f + expf(-acc));
    size_t idx = (size_t)t * PP + pcol;
    xc[idx] = y;
    split_store(y, xch, xcl, idx);
}

// ================= gate prefix scans (softcap + exact linearization) =======
// gi/gf raw from the batched GEMM (g_gates cols 0-7 = i, 8-15 = f).
// m_t = F_t + M_t,  F_t = prefix-sum(f),  a_t = i_t - F_t,
// M_t = max(0, prefix-max(a)).  Weight of key j at query t: e^{a_j - M_t}.
__global__ __launch_bounds__(TT) void gatescan_kernel(
    const float* __restrict__ gates,
    float* __restrict__ a_out, float* __restrict__ M_out)
{
    const int bh = blockIdx.x;          // b*HH + h
    const int b = bh >> 3, h = bh & 7;
    const int t = threadIdx.x;
    __shared__ float sf[TT], sa[TT];
    const size_t gidx = (size_t)(b * TT + t) * 128;
    const float iv = 15.f * tanhf(gates[gidx + h]      * (1.f / 15.f));
    sf[t]          = 15.f * tanhf(gates[gidx + 8 + h]  * (1.f / 15.f));
    __syncthreads();
    #pragma unroll
    for (int st = 1; st < TT; st <<= 1) {
        float add = (t >= st) ? sf[t - st] : 0.f;
        __syncthreads();
        sf[t] += add;
        __syncthreads();
    }
    const float a = iv - sf[t];
    a_out[bh * TT + t] = a;
    sa[t] = a;
    __syncthreads();
    #pragma unroll
    for (int st = 1; st < TT; st <<= 1) {
        float mx = (t >= st) ? sa[t - st] : -3.4e38f;
        __syncthreads();
        sa[t] = fmaxf(sa[t], mx);
        __syncthreads();
    }
    M_out[bh * TT + t] = fmaxf(0.f, sa[t]);
}

// ================= parallel attention-form scan ============================
#define QT 64
#define AP 68                       // row pad (floats); 272B, 16B aligned
#define ASM_BYTES ((4*QT*AP + QT) * 4)

__global__ __launch_bounds__(256) void attn_kernel(
    const float* __restrict__ q, const float* __restrict__ kraw,
    const float* __restrict__ v, const float* __restrict__ aex,
    const float* __restrict__ Mex, const float* __restrict__ oraw,
    const float* __restrict__ skip, const float* __restrict__ rraw,
    const float* __restrict__ hlnw, const float* __restrict__ hlnb,
    bf16* __restrict__ outh, bf16* __restrict__ outl)
{
    const int bh = blockIdx.y, b = bh >> 3, h = bh & 7;
    const int t0 = blockIdx.x * QT;
    extern __shared__ float sm[];
    float* ks = sm;                  // [64][AP]
    float* vs = ks + QT * AP;
    float* qs = vs + QT * AP;
    float* ss = qs + QT * AP;
    float* as_ = ss + QT * AP;       // [64]

    const int tid = threadIdx.x;
    const int qi = tid >> 2, sub = tid & 3;
    const int tq = t0 + qi;
    const size_t qbase = (size_t)(b * TT + tq) * HD + h * DH;

    {
        const int lr = tid >> 2, lc = (tid & 3) * 16;
        const float* src = q + (size_t)(b * TT + t0 + lr) * HD + h * DH + lc;
        #pragma unroll
        for (int i = 0; i < 16; i += 4)
            *(float4*)&qs[lr * AP + lc + i] = *(const float4*)(src + i);
    }
    __syncthreads();

    const float Mt = Mex[bh * TT + tq];
    float num[16];
    #pragma unroll
    for (int i = 0; i < 16; i++) num[i] = 0.f;
    float den = 0.f;

    for (int j0 = 0; j0 <= t0; j0 += QT) {
        {
            const int lr = tid >> 2, lc = (tid & 3) * 16;
            const size_t gb = (size_t)(b * TT + j0 + lr) * HD + h * DH + lc;
            #pragma unroll
            for (int i = 0; i < 16; i += 4) {
                *(float4*)&ks[lr * AP + lc + i] = *(const float4*)(kraw + gb + i);
                *(float4*)&vs[lr * AP + lc + i] = *(const float4*)(v + gb + i);
            }
            if (tid < QT) as_[tid] = aex[bh * TT + j0 + tid];
        }
        __syncthreads();

        float sc[16];
        #pragma unroll
        for (int jj = 0; jj < 16; jj++) sc[jj] = 0.f;
        const float* qrow = &qs[qi * AP];
        #pragma unroll 4
        for (int d = 0; d < DH; d += 4) {
            float q0 = qrow[d], q1 = qrow[d+1], q2 = qrow[d+2], q3 = qrow[d+3];
            #pragma unroll
            for (int jj = 0; jj < 16; jj++) {
                const float* kr = &ks[(sub + 4*jj) * AP + d];
                sc[jj] += q0*kr[0] + q1*kr[1] + q2*kr[2] + q3*kr[3];
            }
        }
        const bool diag = (j0 == t0);
        #pragma unroll
        for (int jj = 0; jj < 16; jj++) {
            const int j = sub + 4*jj;
            float w = (diag && j > qi) ? 0.f
                      : __expf(as_[j] - Mt) * 0.125f * sc[jj];
            ss[qi * AP + j] = w;
            den += w;
        }
        __syncthreads();

        #pragma unroll 8
        for (int j = 0; j < QT; j++) {
            const float s = ss[qi * AP + j];
            const float* vr = &vs[j * AP + sub];
            #pragma unroll
            for (int dd = 0; dd < 16; dd++)
                num[dd] += s * vr[4*dd];
        }
        __syncthreads();
    }

    float sumq = 0.f;
    #pragma unroll
    for (int dd = 0; dd < 16; dd++) sumq += qs[qi * AP + sub + 4*dd];
    den  += __shfl_xor_sync(0xffffffffu, den, 1);
    den  += __shfl_xor_sync(0xffffffffu, den, 2);
    sumq += __shfl_xor_sync(0xffffffffu, sumq, 1);
    sumq += __shfl_xor_sync(0xffffffffu, sumq, 2);
    den = fmaxf(den + __expf(-Mt) * sumq, 1.0f);
    const float rden = 1.f / den;

    float hh[16], s1 = 0.f, s2 = 0.f;
    #pragma unroll
    for (int dd = 0; dd < 16; dd++) {
        const int d = sub + 4*dd;
        const float ov = oraw[qbase + d];
        const float og = 1.f / (1.f + __expf(-ov));
        const float hv = og * num[dd] * rden;
        hh[dd] = hv;
        s1 += hv; s2 += hv * hv;
    }
    s1 += __shfl_xor_sync(0xffffffffu, s1, 1);
    s1 += __shfl_xor_sync(0xffffffffu, s1, 2);
    s2 += __shfl_xor_sync(0xffffffffu, s2, 1);
    s2 += __shfl_xor_sync(0xffffffffu, s2, 2);
    const float mu  = s1 * (1.f / DH);
    const float var = s2 * (1.f / DH) - mu * mu;
    const float rstd = rsqrtf(var + 1e-6f);
    #pragma unroll
    for (int dd = 0; dd < 16; dd++) {
        const int d = sub + 4*dd;
        const float hn = (hh[dd] - mu) * rstd * hlnw[h*DH + d] + hlnb[h*DH + d];
        const float rv = rraw[qbase + d];
        const float sil = rv / (1.f + __expf(-rv));
        const float val = (hn + skip[qbase + d]) * sil;
        split_store(val, outh, outl, qbase + d);
    }
}

// ===========================================================================
extern "C" void kernel_launch(void* const* d_in, const int* in_sizes, int n_in,
                              void* d_out, int out_size)
{
    const float* x      = (const float*)d_in[0];
    const float* ln_w   = (const float*)d_in[1];
    const float* ln_b   = (const float*)d_in[2];
    const float* hln_w  = (const float*)d_in[3];
    const float* hln_b  = (const float*)d_in[4];
    const float* Wl     = (const float*)d_in[5];
    const float* bl     = (const float*)d_in[6];
    const float* Wr     = (const float*)d_in[7];
    const float* br     = (const float*)d_in[8];
    const float* conv_w = (const float*)d_in[9];
    const float* conv_b = (const float*)d_in[10];
    const float* Wskip  = (const float*)d_in[11];
    const float* bskip  = (const float*)d_in[12];
    const float* Wi     = (const float*)d_in[13];
    const float* bi     = (const float*)d_in[14];
    const float* Wf     = (const float*)d_in[15];
    const float* bf_    = (const float*)d_in[16];
    const float* Wo     = (const float*)d_in[17];
    const float* bo     = (const float*)d_in[18];
    const float* Wq     = (const float*)d_in[19];
    const float* bq     = (const float*)d_in[20];
    const float* Wk     = (const float*)d_in[21];
    const float* bk     = (const float*)d_in[22];
    const float* Wv     = (const float*)d_in[23];
    const float* bv     = (const float*)d_in[24];
    const float* Wd     = (const float*)d_in[25];
    const float* bd     = (const float*)d_in[26];
    float* out = (float*)d_out;

    bf16 *xn_h, *xn_l, *xt_h, *xt_l, *xc_h, *xc_l, *cm_h, *cm_l;
    bf16 *WlrT_h, *WlrT_l, *WsT_h, *WsT_l, *WqT_h, *WqT_l;
    bf16 *WkT_h, *WkT_l, *WvT_h, *WvT_l, *WoT_h, *WoT_l, *WdT_h, *WdT_l;
    bf16 *WgT_h, *WgT_l;
    float *xt, *xc, *r, *skip, *q, *k, *v, *o, *gates, *aex, *Mex;
    float *bias_lr, *bias_g;
    cudaGetSymbolAddress((void**)&xn_h, g_xn_h);  cudaGetSymbolAddress((void**)&xn_l, g_xn_l);
    cudaGetSymbolAddress((void**)&xt,   g_xt);
    cudaGetSymbolAddress((void**)&xt_h, g_xt_h);  cudaGetSymbolAddress((void**)&xt_l, g_xt_l);
    cudaGetSymbolAddress((void**)&xc,   g_xc);
    cudaGetSymbolAddress((void**)&xc_h, g_xc_h);  cudaGetSymbolAddress((void**)&xc_l, g_xc_l);
    cudaGetSymbolAddress((void**)&r,    g_r);     cudaGetSymbolAddress((void**)&skip, g_skip);
    cudaGetSymbolAddress((void**)&q,    g_q);     cudaGetSymbolAddress((void**)&k,    g_k);
    cudaGetSymbolAddress((void**)&v,    g_v);     cudaGetSymbolAddress((void**)&o,    g_o);
    cudaGetSymbolAddress((void**)&gates, g_gates);
    cudaGetSymbolAddress((void**)&aex,  g_a);     cudaGetSymbolAddress((void**)&Mex,  g_M);
    cudaGetSymbolAddress((void**)&cm_h, g_cm_h);  cudaGetSymbolAddress((void**)&cm_l, g_cm_l);
    cudaGetSymbolAddress((void**)&WlrT_h, g_WlrT_h); cudaGetSymbolAddress((void**)&WlrT_l, g_WlrT_l);
    cudaGetSymbolAddress((void**)&WsT_h, g_WsT_h); cudaGetSymbolAddress((void**)&WsT_l, g_WsT_l);
    cudaGetSymbolAddress((void**)&WqT_h, g_WqT_h); cudaGetSymbolAddress((void**)&WqT_l, g_WqT_l);
    cudaGetSymbolAddress((void**)&WkT_h, g_WkT_h); cudaGetSymbolAddress((void**)&WkT_l, g_WkT_l);
    cudaGetSymbolAddress((void**)&WvT_h, g_WvT_h); cudaGetSymbolAddress((void**)&WvT_l, g_WvT_l);
    cudaGetSymbolAddress((void**)&WoT_h, g_WoT_h); cudaGetSymbolAddress((void**)&WoT_l, g_WoT_l);
    cudaGetSymbolAddress((void**)&WdT_h, g_WdT_h); cudaGetSymbolAddress((void**)&WdT_l, g_WdT_l);
    cudaGetSymbolAddress((void**)&WgT_h, g_WgT_h); cudaGetSymbolAddress((void**)&WgT_l, g_WgT_l);
    cudaGetSymbolAddress((void**)&bias_lr, g_bias_lr);
    cudaGetSymbolAddress((void**)&bias_g,  g_bias_g);

    cudaFuncSetAttribute(gemm_mma_kernel,
                         cudaFuncAttributeMaxDynamicSharedMemorySize, GSMEM_BYTES);
    cudaFuncSetAttribute(attn_kernel,
                         cudaFuncAttributeMaxDynamicSharedMemorySize, ASM_BYTES);

    const int NLIM_BIG = 1 << 30;

    // 1. merged weight prep (8 transpose+split jobs in one launch)
    {
        PrepJobs pj{};
        const float* Ws[8] = { Wl, Wr, Wskip, Wq, Wk, Wv, Wo, Wd };
        bf16* Ths[8] = { WlrT_h, WlrT_h + (size_t)PP * DD, WsT_h, WqT_h, WkT_h, WvT_h, WoT_h, WdT_h };
        bf16* Tls[8] = { WlrT_l, WlrT_l + (size_t)PP * DD, WsT_l, WqT_l, WkT_l, WvT_l, WoT_l, WdT_l };
        int Ks[8] = { DD, DD, PP, PP, PP, PP, PP, HD };
        int Ns[8] = { PP, HD, HD, HD, HD, HD, HD, DD };
        int cum = 0;
        for (int i = 0; i < 8; i++) {
            pj.W[i] = Ws[i]; pj.Th[i] = Ths[i]; pj.Tl[i] = Tls[i];
            pj.K[i] = Ks[i]; pj.N[i] = Ns[i];
            pj.cum[i] = cum;
            cum += (Ns[i] / 32) * (Ks[i] / 32);
        }
        pj.cum[8] = cum;
        prep_all_kernel<<<cum, 256>>>(pj);
    }
    // 2. gate weights + packed biases
    misc_prep_kernel<<<139, 256>>>(Wi, Wf, bl, br, bi, bf_);

    // 3. layernorm -> xn splits
    ln_split_kernel<<<NTOK, 256>>>(x, ln_w, ln_b, xn_h, xn_l);

    // 4. merged [xt | r] = xn @ [Wl | Wr] + [bl | br]
    {
        GemmParams p{}; p.K = DD;
        p.jobs[0] = { xn_h, xn_l, WlrT_h, WlrT_l, bias_lr, nullptr,
                      xt, xt_h, xt_l, r, PP, PP, HD, NLIM_BIG };
        gemm_mma_kernel<<<dim3(2560/128, NTOK/128, 1), 256, GSMEM_BYTES>>>(p);
    }
    // 5. conv + silu -> xc
    conv_silu_kernel<<<dim3(NTOK, PP/256), 256>>>(xt, conv_w, conv_b, xc, xc_h, xc_l);

    // 6. six P->HD(128) projections in one batched launch (incl. gates)
    {
        GemmParams p{}; p.K = PP;
        p.jobs[0] = { xc_h, xc_l, WsT_h, WsT_l, bskip, nullptr, skip, nullptr, nullptr,
                      nullptr, NLIM_BIG, HD, 0, NLIM_BIG };
        p.jobs[1] = { xc_h, xc_l, WqT_h, WqT_l, bq, nullptr, q, nullptr, nullptr,
                      nullptr, NLIM_BIG, HD, 0, NLIM_BIG };
        p.jobs[2] = { xc_h, xc_l, WkT_h, WkT_l, bk, nullptr, k, nullptr, nullptr,
                      nullptr, NLIM_BIG, HD, 0, NLIM_BIG };
        p.jobs[3] = { xt_h, xt_l, WvT_h, WvT_l, bv, nullptr, v, nullptr, nullptr,
                      nullptr, NLIM_BIG, HD, 0, NLIM_BIG };
        p.jobs[4] = { xt_h, xt_l, WoT_h, WoT_l, bo, nullptr, o, nullptr, nullptr,
                      nullptr, NLIM_BIG, HD, 0, NLIM_BIG };
        p.jobs[5] = { xc_h, xc_l, WgT_h, WgT_l, bias_g, nullptr, gates, nullptr, nullptr,
                      nullptr, NLIM_BIG, 128, 0, 128 };
        gemm_mma_kernel<<<dim3(HD/128, NTOK/128, 6), 256, GSMEM_BYTES>>>(p);
    }
    // 7. gate softcap + prefix scans
    gatescan_kernel<<<BB*HH, TT>>>(gates, aex, Mex);

    // 8. parallel attention-form scan -> comb splits
    attn_kernel<<<dim3(TT/QT, BB*HH), 256, ASM_BYTES>>>(
        q, k, v, aex, Mex, o, skip, r, hln_w, hln_b, cm_h, cm_l);

    // 9. out = comb @ Wd + bd + x
    {
        GemmParams p{}; p.K = HD;
        p.jobs[0] = { cm_h, cm_l, WdT_h, WdT_l, bd, x, out, nullptr, nullptr,
                      nullptr, NLIM_BIG, DD, 0, NLIM_BIG };
        gemm_mma_kernel<<<dim3(DD/128, NTOK/128, 1), 256, GSMEM_BYTES>>>(p);
    }
}

// round 9
// speedup vs baseline: 1.2289x; 1.2289x over previous
#include <cuda_runtime.h>
#include <cuda_bf16.h>
#include <cstdint>
#include <math.h>

typedef __nv_bfloat16 bf16;

// Problem constants
#define BB 4
#define TT 512
#define DD 1024
#define HH 8
#define DH 64
#define HD 512
#define PP 2048
#define NTOK (BB*TT)          // 2048 tokens

// ================= scratch (device globals) =================================
__device__ bf16  g_xn_h[NTOK*DD], g_xn_l[NTOK*DD];
__device__ float g_xt  [NTOK*PP];
__device__ bf16  g_xt_h[NTOK*PP], g_xt_l[NTOK*PP];
__device__ float g_xc  [NTOK*PP];
__device__ bf16  g_xc_h[NTOK*PP], g_xc_l[NTOK*PP];
__device__ float g_r   [NTOK*HD], g_skip[NTOK*HD];
__device__ float g_q   [NTOK*HD], g_k   [NTOK*HD];
__device__ float g_v   [NTOK*HD], g_o   [NTOK*HD];
__device__ float g_gates[NTOK*128];      // raw i/f gate pre-activations (cols 0-15)
__device__ float g_a   [BB*HH*TT], g_M [BB*HH*TT];
__device__ bf16  g_cm_h[NTOK*HD], g_cm_l[NTOK*HD];
// transposed + split weights
__device__ bf16 g_WlrT_h[2560*DD], g_WlrT_l[2560*DD];   // [Wl | Wr] cols, K=1024
__device__ bf16 g_WsT_h[HD*PP], g_WsT_l[HD*PP];
__device__ bf16 g_WqT_h[HD*PP], g_WqT_l[HD*PP];
__device__ bf16 g_WkT_h[HD*PP], g_WkT_l[HD*PP];
__device__ bf16 g_WvT_h[HD*PP], g_WvT_l[HD*PP];
__device__ bf16 g_WoT_h[HD*PP], g_WoT_l[HD*PP];
__device__ bf16 g_WdT_h[DD*HD], g_WdT_l[DD*HD];
__device__ bf16 g_WgT_h[128*PP], g_WgT_l[128*PP];       // rows 0-7 Wi, 8-15 Wf, rest 0
__device__ float g_bias_lr[2560];
__device__ float g_bias_g[128];

__device__ __forceinline__ void split_store(float v, bf16* ph, bf16* pl, size_t i) {
    bf16 h = __float2bfloat16(v);
    ph[i] = h;
    pl[i] = __float2bfloat16(v - __bfloat162float(h));
}

__device__ __forceinline__ uint32_t smem_u32(const void* p) {
    uint32_t a;
    asm("{ .reg .u64 t; cvta.to.shared.u64 t, %1; cvt.u32.u64 %0, t; }"
        : "=r"(a) : "l"(p));
    return a;
}
__device__ __forceinline__ void cp16(uint32_t s, const void* g) {
    asm volatile("cp.async.cg.shared.global [%0], [%1], 16;" :: "r"(s), "l"(g));
}
__device__ __forceinline__ void ldm4(uint32_t addr, uint32_t* r) {
    asm volatile("ldmatrix.sync.aligned.m8n8.x4.shared.b16 {%0,%1,%2,%3}, [%4];"
                 : "=r"(r[0]), "=r"(r[1]), "=r"(r[2]), "=r"(r[3]) : "r"(addr));
}
__device__ __forceinline__ void mma16816(float* c, const uint32_t* a,
                                         uint32_t b0, uint32_t b1) {
    asm volatile("mma.sync.aligned.m16n8k16.row.col.f32.bf16.bf16.f32 "
        "{%0,%1,%2,%3}, {%4,%5,%6,%7}, {%8,%9}, {%0,%1,%2,%3};"
        : "+f"(c[0]), "+f"(c[1]), "+f"(c[2]), "+f"(c[3])
        : "r"(a[0]), "r"(a[1]), "r"(a[2]), "r"(a[3]), "r"(b0), "r"(b1));
}

// ================= merged weight transpose + split =========================
struct PrepJobs {
    const float* W[8];
    bf16 *Th[8], *Tl[8];
    int K[8], N[8], cum[9];
};
__global__ __launch_bounds__(256) void prep_all_kernel(PrepJobs pj)
{
    int bx = blockIdx.x, j = 0;
    #pragma unroll
    for (int i = 0; i < 8; i++) if (bx >= pj.cum[i + 1]) j = i + 1;
    const int local = bx - pj.cum[j];
    const int K = pj.K[j], N = pj.N[j];
    const int nbn = N / 32;
    const int n0 = (local % nbn) * 32, k0 = (local / nbn) * 32;
    const float* W = pj.W[j];
    bf16 *Th = pj.Th[j], *Tl = pj.Tl[j];

    __shared__ float tile[32][33];
    int tx = threadIdx.x & 31, ty = threadIdx.x >> 5;
    for (int r = ty; r < 32; r += 8)
        tile[r][tx] = W[(size_t)(k0 + r) * N + n0 + tx];
    __syncthreads();
    for (int r = ty; r < 32; r += 8) {
        float v = tile[tx][r];
        split_store(v, Th, Tl, (size_t)(n0 + r) * K + k0 + tx);
    }
}

// gate weights (Wi|Wf -> 16 rows of WgT) + packed biases
__global__ __launch_bounds__(256) void misc_prep_kernel(
    const float* __restrict__ Wi, const float* __restrict__ Wf,
    const float* __restrict__ bl, const float* __restrict__ br,
    const float* __restrict__ bi, const float* __restrict__ bfp)
{
    const int blk = blockIdx.x, tid = threadIdx.x;
    if (blk < 128) {                       // WgT: 2048*16 elements
        int idx = blk * 256 + tid;         // 0..32767
        int k = idx >> 4, n = idx & 15;
        float v = (n < 8) ? Wi[k * HH + n] : Wf[k * HH + (n - 8)];
        split_store(v, g_WgT_h, g_WgT_l, (size_t)n * PP + k);
    } else if (blk < 138) {                // bias_lr: 2560
        int idx = (blk - 128) * 256 + tid;
        if (idx < 2560)
            g_bias_lr[idx] = (idx < PP) ? bl[idx] : br[idx - PP];
    } else {                               // bias_g: 128
        if (tid < 128)
            g_bias_g[tid] = (tid < 8) ? bi[tid] : (tid < 16 ? bfp[tid - 8] : 0.f);
    }
}

// ================= layernorm + bf16 split ==================================
__global__ __launch_bounds__(256) void ln_split_kernel(
    const float* __restrict__ x, const float* __restrict__ w,
    const float* __restrict__ b, bf16* __restrict__ oh, bf16* __restrict__ ol)
{
    int t = blockIdx.x;
    const float* row = x + (size_t)t * DD;
    float s = 0.f, s2 = 0.f;
    for (int i = threadIdx.x; i < DD; i += 256) {
        float v = row[i]; s += v; s2 += v * v;
    }
    __shared__ float sh[16];
    int warp = threadIdx.x >> 5, lane = threadIdx.x & 31;
    #pragma unroll
    for (int o = 16; o; o >>= 1) {
        s  += __shfl_xor_sync(0xffffffffu, s,  o);
        s2 += __shfl_xor_sync(0xffffffffu, s2, o);
    }
    if (lane == 0) { sh[warp] = s; sh[8 + warp] = s2; }
    __syncthreads();
    if (threadIdx.x == 0) {
        float ts = 0.f, ts2 = 0.f;
        #pragma unroll
        for (int i = 0; i < 8; i++) { ts += sh[i]; ts2 += sh[8 + i]; }
        float mu  = ts  * (1.f / DD);
        float var = ts2 * (1.f / DD) - mu * mu;
        sh[0] = mu; sh[1] = rsqrtf(var + 1e-6f);
    }
    __syncthreads();
    float mu = sh[0], rstd = sh[1];
    for (int i = threadIdx.x; i < DD; i += 256) {
        float y = (row[i] - mu) * rstd * w[i] + b[i];
        split_store(y, oh, ol, (size_t)t * DD + i);
    }
}

// ================= mma.sync split-bf16 GEMM (BK=32, 2 CTAs/SM) =============
struct GemmJob {
    const bf16 *Ah, *Al, *Bh, *Bl;
    const float *bias, *res;
    float *out;
    bf16 *oh, *ol;
    float *out2;                  // columns >= ncut go here (ld = ldo2)
    int ncut, ldo, ldo2, nlimit;  // nlimit: skip CTAs with bn >= nlimit
};
struct GemmParams { GemmJob jobs[6]; int K; };

#define PADK 40                        // halves per smem row (32 + 8 pad)
#define OPT  (128*PADK)                // halves per operand tile
#define STG4 (4*OPT)                   // halves per stage (Ah,Al,Bh,Bl)
#define GSMEM_BYTES (2*STG4*2)         // 81920 B  -> 2 CTAs/SM

__global__ __launch_bounds__(256, 2) void gemm_mma_kernel(GemmParams p)
{
    const GemmJob J = p.jobs[blockIdx.z];
    const int bm = blockIdx.y * 128, bn = blockIdx.x * 128;
    if (bn >= J.nlimit) return;

    extern __shared__ bf16 smg[];
    const uint32_t sbase = smem_u32(smg);
    const int K = p.K;
    const int tid = threadIdx.x, lane = tid & 31, wid = tid >> 5;
    const int warpM = wid & 3, warpN = wid >> 2;    // 4 x 2 warps, tile 32x64

    const bf16* gsrc[4];
    gsrc[0] = J.Ah + (size_t)bm * K;
    gsrc[1] = J.Al + (size_t)bm * K;
    gsrc[2] = J.Bh + (size_t)bn * K;
    gsrc[3] = J.Bl + (size_t)bn * K;

    // loader: 2 threads per row; each thread 2x16B chunks
    const int lrow = tid >> 1;
    const int lcol = (tid & 1) * 16;   // element offset (0 or 16)
    const uint32_t swr = sbase + (uint32_t)(lrow * PADK + lcol) * 2;

    float acc[2][8][4];
    #pragma unroll
    for (int i = 0; i < 2; i++)
        #pragma unroll
        for (int j = 0; j < 8; j++)
            #pragma unroll
            for (int e = 0; e < 4; e++) acc[i][j][e] = 0.f;

    const int NT = K / 32;
    {
        #pragma unroll
        for (int w = 0; w < 4; w++) {
            const bf16* g = gsrc[w] + (size_t)lrow * K + lcol;
            uint32_t s = swr + (uint32_t)(w * OPT) * 2;
            cp16(s, g); cp16(s + 16, g + 8);
        }
        asm volatile("cp.async.commit_group;");
    }

    int buf = 0;
    for (int kt = 0; kt < NT; kt++) {
        if (kt + 1 < NT) {
            const int k0 = (kt + 1) * 32;
            #pragma unroll
            for (int w = 0; w < 4; w++) {
                const bf16* g = gsrc[w] + (size_t)lrow * K + k0 + lcol;
                uint32_t s = swr + (uint32_t)((buf ^ 1) * STG4 + w * OPT) * 2;
                cp16(s, g); cp16(s + 16, g + 8);
            }
            asm volatile("cp.async.commit_group;");
            asm volatile("cp.async.wait_group 1;");
        } else {
            asm volatile("cp.async.wait_group 0;");
        }
        __syncthreads();

        const uint32_t stg = sbase + (uint32_t)(buf * STG4) * 2;
        #pragma unroll
        for (int ks = 0; ks < 2; ks++) {
            const int koff = ks * 16 + ((lane >> 4) << 3);
            const int rsel = lane & 15;
            uint32_t a[2][2][4], b[2][4][4];
            #pragma unroll
            for (int op = 0; op < 2; op++)
                #pragma unroll
                for (int i = 0; i < 2; i++) {
                    const int row = warpM * 32 + i * 16 + rsel;
                    ldm4(stg + (uint32_t)(op * OPT + row * PADK + koff) * 2,
                         a[op][i]);
                }
            #pragma unroll
            for (int op = 0; op < 2; op++)
                #pragma unroll
                for (int j = 0; j < 4; j++) {
                    const int row = warpN * 64 + j * 16 + rsel;
                    ldm4(stg + (uint32_t)((2 + op) * OPT + row * PADK + koff) * 2,
                         b[op][j]);
                }
            #pragma unroll
            for (int ps = 0; ps < 3; ps++) {
                const int aop = (ps == 2) ? 1 : 0;
                const int bop = (ps == 1) ? 1 : 0;
                #pragma unroll
                for (int i = 0; i < 2; i++)
                    #pragma unroll
                    for (int j = 0; j < 8; j++)
                        mma16816(acc[i][j], a[aop][i],
                                 b[bop][j >> 1][j & 1],
                                 b[bop][j >> 1][(j & 1) + 2]);
            }
        }
        __syncthreads();
        buf ^= 1;
    }

    const int er = (lane >> 2);
    const int ec = (lane & 3) * 2;
    #pragma unroll
    for (int i = 0; i < 2; i++) {
        #pragma unroll
        for (int j = 0; j < 8; j++) {
            const int row0 = bm + warpM * 32 + i * 16 + er;
            const int col0 = bn + warpN * 64 + j * 8 + ec;
            #pragma unroll
            for (int e = 0; e < 4; e++) {
                const int row = row0 + (e >> 1) * 8;
                const int col = col0 + (e & 1);
                float v = acc[i][j][e] + J.bias[col];
                if (col >= J.ncut) {
                    J.out2[(size_t)row * J.ldo2 + (col - J.ncut)] = v;
                } else {
                    if (J.res) v += J.res[(size_t)row * J.ldo + col];
                    const size_t idx = (size_t)row * J.ldo + col;
                    J.out[idx] = v;
                    if (J.oh) split_store(v, J.oh, J.ol, idx);
                }
            }
        }
    }
}

// ================= causal feature-conv + silu + split ======================
__global__ __launch_bounds__(256) void conv_silu_kernel(
    const float* __restrict__ xt, const float* __restrict__ cw,
    const float* __restrict__ cbp, float* __restrict__ xc,
    bf16* __restrict__ xch, bf16* __restrict__ xcl)
{
    int t = blockIdx.x;
    int pcol = blockIdx.y * 256 + threadIdx.x;
    const float* row = xt + (size_t)t * PP;
    float w0 = cw[0], w1 = cw[1], w2 = cw[2], w3 = cw[3];
    float acc = row[pcol] * w3;
    if (pcol >= 1) acc += row[pcol - 1] * w2;
    if (pcol >= 2) acc += row[pcol - 2] * w1;
    if (pcol >= 3) acc += row[pcol - 3] * w0;
    acc += cbp[0];
    float y = acc / (1.f + expf(-acc));
    size_t idx = (size_t)t * PP + pcol;
    xc[idx] = y;
    split_store(y, xch, xcl, idx);
}

// ================= gate prefix scans (softcap + exact linearization) =======
__global__ __launch_bounds__(TT) void gatescan_kernel(
    const float* __restrict__ gates,
    float* __restrict__ a_out, float* __restrict__ M_out)
{
    const int bh = blockIdx.x;          // b*HH + h
    const int b = bh >> 3, h = bh & 7;
    const int t = threadIdx.x;
    __shared__ float sf[TT], sa[TT];
    const size_t gidx = (size_t)(b * TT + t) * 128;
    const float iv = 15.f * tanhf(gates[gidx + h]      * (1.f / 15.f));
    sf[t]          = 15.f * tanhf(gates[gidx + 8 + h]  * (1.f / 15.f));
    __syncthreads();
    #pragma unroll
    for (int st = 1; st < TT; st <<= 1) {
        float add = (t >= st) ? sf[t - st] : 0.f;
        __syncthreads();
        sf[t] += add;
        __syncthreads();
    }
    const float a = iv - sf[t];
    a_out[bh * TT + t] = a;
    sa[t] = a;
    __syncthreads();
    #pragma unroll
    for (int st = 1; st < TT; st <<= 1) {
        float mx = (t >= st) ? sa[t - st] : -3.4e38f;
        __syncthreads();
        sa[t] = fmaxf(sa[t], mx);
        __syncthreads();
    }
    M_out[bh * TT + t] = fmaxf(0.f, sa[t]);
}

// ================= parallel attention-form scan ============================
#define QT 64
#define AP 68                       // row pad (floats); 272B, 16B aligned
#define ASM_BYTES ((4*QT*AP + QT) * 4)

__global__ __launch_bounds__(256) void attn_kernel(
    const float* __restrict__ q, const float* __restrict__ kraw,
    const float* __restrict__ v, const float* __restrict__ aex,
    const float* __restrict__ Mex, const float* __restrict__ oraw,
    const float* __restrict__ skip, const float* __restrict__ rraw,
    const float* __restrict__ hlnw, const float* __restrict__ hlnb,
    bf16* __restrict__ outh, bf16* __restrict__ outl)
{
    const int bh = blockIdx.y, b = bh >> 3, h = bh & 7;
    const int t0 = blockIdx.x * QT;
    extern __shared__ float sm[];
    float* ks = sm;                  // [64][AP]
    float* vs = ks + QT * AP;
    float* qs = vs + QT * AP;
    float* ss = qs + QT * AP;
    float* as_ = ss + QT * AP;       // [64]

    const int tid = threadIdx.x;
    const int qi = tid >> 2, sub = tid & 3;
    const int tq = t0 + qi;
    const size_t qbase = (size_t)(b * TT + tq) * HD + h * DH;

    {
        const int lr = tid >> 2, lc = (tid & 3) * 16;
        const float* src = q + (size_t)(b * TT + t0 + lr) * HD + h * DH + lc;
        #pragma unroll
        for (int i = 0; i < 16; i += 4)
            *(float4*)&qs[lr * AP + lc + i] = *(const float4*)(src + i);
    }
    __syncthreads();

    const float Mt = Mex[bh * TT + tq];
    float num[16];
    #pragma unroll
    for (int i = 0; i < 16; i++) num[i] = 0.f;
    float den = 0.f;

    for (int j0 = 0; j0 <= t0; j0 += QT) {
        {
            const int lr = tid >> 2, lc = (tid & 3) * 16;
            const size_t gb = (size_t)(b * TT + j0 + lr) * HD + h * DH + lc;
            #pragma unroll
            for (int i = 0; i < 16; i += 4) {
                *(float4*)&ks[lr * AP + lc + i] = *(const float4*)(kraw + gb + i);
                *(float4*)&vs[lr * AP + lc + i] = *(const float4*)(v + gb + i);
            }
            if (tid < QT) as_[tid] = aex[bh * TT + j0 + tid];
        }
        __syncthreads();

        float sc[16];
        #pragma unroll
        for (int jj = 0; jj < 16; jj++) sc[jj] = 0.f;
        const float* qrow = &qs[qi * AP];
        #pragma unroll 4
        for (int d = 0; d < DH; d += 4) {
            float q0 = qrow[d], q1 = qrow[d+1], q2 = qrow[d+2], q3 = qrow[d+3];
            #pragma unroll
            for (int jj = 0; jj < 16; jj++) {
                const float* kr = &ks[(sub + 4*jj) * AP + d];
                sc[jj] += q0*kr[0] + q1*kr[1] + q2*kr[2] + q3*kr[3];
            }
        }
        const bool diag = (j0 == t0);
        #pragma unroll
        for (int jj = 0; jj < 16; jj++) {
            const int j = sub + 4*jj;
            float w = (diag && j > qi) ? 0.f
                      : __expf(as_[j] - Mt) * 0.125f * sc[jj];
            ss[qi * AP + j] = w;
            den += w;
        }
        __syncthreads();

        #pragma unroll 8
        for (int j = 0; j < QT; j++) {
            const float s = ss[qi * AP + j];
            const float* vr = &vs[j * AP + sub];
            #pragma unroll
            for (int dd = 0; dd < 16; dd++)
                num[dd] += s * vr[4*dd];
        }
        __syncthreads();
    }

    float sumq = 0.f;
    #pragma unroll
    for (int dd = 0; dd < 16; dd++) sumq += qs[qi * AP + sub + 4*dd];
    den  += __shfl_xor_sync(0xffffffffu, den, 1);
    den  += __shfl_xor_sync(0xffffffffu, den, 2);
    sumq += __shfl_xor_sync(0xffffffffu, sumq, 1);
    sumq += __shfl_xor_sync(0xffffffffu, sumq, 2);
    den = fmaxf(den + __expf(-Mt) * sumq, 1.0f);
    const float rden = 1.f / den;

    float hh[16], s1 = 0.f, s2 = 0.f;
    #pragma unroll
    for (int dd = 0; dd < 16; dd++) {
        const int d = sub + 4*dd;
        const float ov = oraw[qbase + d];
        const float og = 1.f / (1.f + __expf(-ov));
        const float hv = og * num[dd] * rden;
        hh[dd] = hv;
        s1 += hv; s2 += hv * hv;
    }
    s1 += __shfl_xor_sync(0xffffffffu, s1, 1);
    s1 += __shfl_xor_sync(0xffffffffu, s1, 2);
    s2 += __shfl_xor_sync(0xffffffffu, s2, 1);
    s2 += __shfl_xor_sync(0xffffffffu, s2, 2);
    const float mu  = s1 * (1.f / DH);
    const float var = s2 * (1.f / DH) - mu * mu;
    const float rstd = rsqrtf(var + 1e-6f);
    #pragma unroll
    for (int dd = 0; dd < 16; dd++) {
        const int d = sub + 4*dd;
        const float hn = (hh[dd] - mu) * rstd * hlnw[h*DH + d] + hlnb[h*DH + d];
        const float rv = rraw[qbase + d];
        const float sil = rv / (1.f + __expf(-rv));
        const float val = (hn + skip[qbase + d]) * sil;
        split_store(val, outh, outl, qbase + d);
    }
}

// ===========================================================================
extern "C" void kernel_launch(void* const* d_in, const int* in_sizes, int n_in,
                              void* d_out, int out_size)
{
    const float* x      = (const float*)d_in[0];
    const float* ln_w   = (const float*)d_in[1];
    const float* ln_b   = (const float*)d_in[2];
    const float* hln_w  = (const float*)d_in[3];
    const float* hln_b  = (const float*)d_in[4];
    const float* Wl     = (const float*)d_in[5];
    const float* bl     = (const float*)d_in[6];
    const float* Wr     = (const float*)d_in[7];
    const float* br     = (const float*)d_in[8];
    const float* conv_w = (const float*)d_in[9];
    const float* conv_b = (const float*)d_in[10];
    const float* Wskip  = (const float*)d_in[11];
    const float* bskip  = (const float*)d_in[12];
    const float* Wi     = (const float*)d_in[13];
    const float* bi     = (const float*)d_in[14];
    const float* Wf     = (const float*)d_in[15];
    const float* bf_    = (const float*)d_in[16];
    const float* Wo     = (const float*)d_in[17];
    const float* bo     = (const float*)d_in[18];
    const float* Wq     = (const float*)d_in[19];
    const float* bq     = (const float*)d_in[20];
    const float* Wk     = (const float*)d_in[21];
    const float* bk     = (const float*)d_in[22];
    const float* Wv     = (const float*)d_in[23];
    const float* bv     = (const float*)d_in[24];
    const float* Wd     = (const float*)d_in[25];
    const float* bd     = (const float*)d_in[26];
    float* out = (float*)d_out;

    bf16 *xn_h, *xn_l, *xt_h, *xt_l, *xc_h, *xc_l, *cm_h, *cm_l;
    bf16 *WlrT_h, *WlrT_l, *WsT_h, *WsT_l, *WqT_h, *WqT_l;
    bf16 *WkT_h, *WkT_l, *WvT_h, *WvT_l, *WoT_h, *WoT_l, *WdT_h, *WdT_l;
    bf16 *WgT_h, *WgT_l;
    float *xt, *xc, *r, *skip, *q, *k, *v, *o, *gates, *aex, *Mex;
    float *bias_lr, *bias_g;
    cudaGetSymbolAddress((void**)&xn_h, g_xn_h);  cudaGetSymbolAddress((void**)&xn_l, g_xn_l);
    cudaGetSymbolAddress((void**)&xt,   g_xt);
    cudaGetSymbolAddress((void**)&xt_h, g_xt_h);  cudaGetSymbolAddress((void**)&xt_l, g_xt_l);
    cudaGetSymbolAddress((void**)&xc,   g_xc);
    cudaGetSymbolAddress((void**)&xc_h, g_xc_h);  cudaGetSymbolAddress((void**)&xc_l, g_xc_l);
    cudaGetSymbolAddress((void**)&r,    g_r);     cudaGetSymbolAddress((void**)&skip, g_skip);
    cudaGetSymbolAddress((void**)&q,    g_q);     cudaGetSymbolAddress((void**)&k,    g_k);
    cudaGetSymbolAddress((void**)&v,    g_v);     cudaGetSymbolAddress((void**)&o,    g_o);
    cudaGetSymbolAddress((void**)&gates, g_gates);
    cudaGetSymbolAddress((void**)&aex,  g_a);     cudaGetSymbolAddress((void**)&Mex,  g_M);
    cudaGetSymbolAddress((void**)&cm_h, g_cm_h);  cudaGetSymbolAddress((void**)&cm_l, g_cm_l);
    cudaGetSymbolAddress((void**)&WlrT_h, g_WlrT_h); cudaGetSymbolAddress((void**)&WlrT_l, g_WlrT_l);
    cudaGetSymbolAddress((void**)&WsT_h, g_WsT_h); cudaGetSymbolAddress((void**)&WsT_l, g_WsT_l);
    cudaGetSymbolAddress((void**)&WqT_h, g_WqT_h); cudaGetSymbolAddress((void**)&WqT_l, g_WqT_l);
    cudaGetSymbolAddress((void**)&WkT_h, g_WkT_h); cudaGetSymbolAddress((void**)&WkT_l, g_WkT_l);
    cudaGetSymbolAddress((void**)&WvT_h, g_WvT_h); cudaGetSymbolAddress((void**)&WvT_l, g_WvT_l);
    cudaGetSymbolAddress((void**)&WoT_h, g_WoT_h); cudaGetSymbolAddress((void**)&WoT_l, g_WoT_l);
    cudaGetSymbolAddress((void**)&WdT_h, g_WdT_h); cudaGetSymbolAddress((void**)&WdT_l, g_WdT_l);
    cudaGetSymbolAddress((void**)&WgT_h, g_WgT_h); cudaGetSymbolAddress((void**)&WgT_l, g_WgT_l);
    cudaGetSymbolAddress((void**)&bias_lr, g_bias_lr);
    cudaGetSymbolAddress((void**)&bias_g,  g_bias_g);

    cudaFuncSetAttribute(gemm_mma_kernel,
                         cudaFuncAttributeMaxDynamicSharedMemorySize, GSMEM_BYTES);
    cudaFuncSetAttribute(attn_kernel,
                         cudaFuncAttributeMaxDynamicSharedMemorySize, ASM_BYTES);

    const int NLIM_BIG = 1 << 30;

    // 1. merged weight prep (8 transpose+split jobs in one launch)
    {
        PrepJobs pj{};
        const float* Ws[8] = { Wl, Wr, Wskip, Wq, Wk, Wv, Wo, Wd };
        bf16* Ths[8] = { WlrT_h, WlrT_h + (size_t)PP * DD, WsT_h, WqT_h, WkT_h, WvT_h, WoT_h, WdT_h };
        bf16* Tls[8] = { WlrT_l, WlrT_l + (size_t)PP * DD, WsT_l, WqT_l, WkT_l, WvT_l, WoT_l, WdT_l };
        int Ks[8] = { DD, DD, PP, PP, PP, PP, PP, HD };
        int Ns[8] = { PP, HD, HD, HD, HD, HD, HD, DD };
        int cum = 0;
        for (int i = 0; i < 8; i++) {
            pj.W[i] = Ws[i]; pj.Th[i] = Ths[i]; pj.Tl[i] = Tls[i];
            pj.K[i] = Ks[i]; pj.N[i] = Ns[i];
            pj.cum[i] = cum;
            cum += (Ns[i] / 32) * (Ks[i] / 32);
        }
        pj.cum[8] = cum;
        prep_all_kernel<<<cum, 256>>>(pj);
    }
    // 2. gate weights + packed biases
    misc_prep_kernel<<<139, 256>>>(Wi, Wf, bl, br, bi, bf_);

    // 3. layernorm -> xn splits
    ln_split_kernel<<<NTOK, 256>>>(x, ln_w, ln_b, xn_h, xn_l);

    // 4. merged [xt | r] = xn @ [Wl | Wr] + [bl | br]
    {
        GemmParams p{}; p.K = DD;
        p.jobs[0] = { xn_h, xn_l, WlrT_h, WlrT_l, bias_lr, nullptr,
                      xt, xt_h, xt_l, r, PP, PP, HD, NLIM_BIG };
        gemm_mma_kernel<<<dim3(2560/128, NTOK/128, 1), 256, GSMEM_BYTES>>>(p);
    }
    // 5. conv + silu -> xc
    conv_silu_kernel<<<dim3(NTOK, PP/256), 256>>>(xt, conv_w, conv_b, xc, xc_h, xc_l);

    // 6. six P->HD(128) projections in one batched launch (incl. gates)
    {
        GemmParams p{}; p.K = PP;
        p.jobs[0] = { xc_h, xc_l, WsT_h, WsT_l, bskip, nullptr, skip, nullptr, nullptr,
                      nullptr, NLIM_BIG, HD, 0, NLIM_BIG };
        p.jobs[1] = { xc_h, xc_l, WqT_h, WqT_l, bq, nullptr, q, nullptr, nullptr,
                      nullptr, NLIM_BIG, HD, 0, NLIM_BIG };
        p.jobs[2] = { xc_h, xc_l, WkT_h, WkT_l, bk, nullptr, k, nullptr, nullptr,
                      nullptr, NLIM_BIG, HD, 0, NLIM_BIG };
        p.jobs[3] = { xt_h, xt_l, WvT_h, WvT_l, bv, nullptr, v, nullptr, nullptr,
                      nullptr, NLIM_BIG, HD, 0, NLIM_BIG };
        p.jobs[4] = { xt_h, xt_l, WoT_h, WoT_l, bo, nullptr, o, nullptr, nullptr,
                      nullptr, NLIM_BIG, HD, 0, NLIM_BIG };
        p.jobs[5] = { xc_h, xc_l, WgT_h, WgT_l, bias_g, nullptr, gates, nullptr, nullptr,
                      nullptr, NLIM_BIG, 128, 0, 128 };
        gemm_mma_kernel<<<dim3(HD/128, NTOK/128, 6), 256, GSMEM_BYTES>>>(p);
    }
    // 7. gate softcap + prefix scans
    gatescan_kernel<<<BB*HH, TT>>>(gates, aex, Mex);

    // 8. parallel attention-form scan -> comb splits
    attn_kernel<<<dim3(TT/QT, BB*HH), 256, ASM_BYTES>>>(
        q, k, v, aex, Mex, o, skip, r, hln_w, hln_b, cm_h, cm_l);

    // 9. out = comb @ Wd + bd + x
    {
        GemmParams p{}; p.K = HD;
        p.jobs[0] = { cm_h, cm_l, WdT_h, WdT_l, bd, x, out, nullptr, nullptr,
                      nullptr, NLIM_BIG, DD, 0, NLIM_BIG };
        gemm_mma_kernel<<<dim3(DD/128, NTOK/128, 1), 256, GSMEM_BYTES>>>(p);
    }
}

// round 10
// speedup vs baseline: 1.3920x; 1.1327x over previous
#include <cuda_runtime.h>
#include <cuda_fp16.h>
#include <cstdint>
#include <math.h>

typedef __half fp16;

// Problem constants
#define BB 4
#define TT 512
#define DD 1024
#define HH 8
#define DH 64
#define HD 512
#define PP 2048
#define NTOK (BB*TT)          // 2048 tokens

// ================= scratch (device globals) =================================
__device__ fp16  g_xn_h[NTOK*DD], g_xn_l[NTOK*DD];
__device__ float g_xt  [NTOK*PP];
__device__ fp16  g_xt_h[NTOK*PP], g_xt_l[NTOK*PP];
__device__ float g_xc  [NTOK*PP];
__device__ fp16  g_xc_h[NTOK*PP], g_xc_l[NTOK*PP];
__device__ float g_r   [NTOK*HD], g_skip[NTOK*HD];
__device__ float g_q   [NTOK*HD], g_k   [NTOK*HD];
__device__ float g_v   [NTOK*HD], g_o   [NTOK*HD];
__device__ float g_ig  [NTOK*HH], g_fg  [NTOK*HH];
__device__ float g_a   [BB*HH*TT], g_M [BB*HH*TT];
__device__ fp16  g_cm_h[NTOK*HD], g_cm_l[NTOK*HD];
// transposed weights (single fp16): WT[N,K]
__device__ fp16 g_WlrT[2560*DD];      // [Wl | Wr] cols, K=1024
__device__ fp16 g_WsT[HD*PP], g_WqT[HD*PP], g_WkT[HD*PP];
__device__ fp16 g_WvT[HD*PP], g_WoT[HD*PP], g_WdT[DD*HD];
__device__ float g_bias_lr[2560];

__device__ __forceinline__ void split_store(float v, fp16* ph, fp16* pl, size_t i) {
    fp16 h = __float2half(v);
    ph[i] = h;
    pl[i] = __float2half(v - __half2float(h));
}

__device__ __forceinline__ uint32_t smem_u32(const void* p) {
    uint32_t a;
    asm("{ .reg .u64 t; cvta.to.shared.u64 t, %1; cvt.u32.u64 %0, t; }"
        : "=r"(a) : "l"(p));
    return a;
}
__device__ __forceinline__ void cp16(uint32_t s, const void* g) {
    asm volatile("cp.async.cg.shared.global [%0], [%1], 16;" :: "r"(s), "l"(g));
}
__device__ __forceinline__ void ldm4(uint32_t addr, uint32_t* r) {
    asm volatile("ldmatrix.sync.aligned.m8n8.x4.shared.b16 {%0,%1,%2,%3}, [%4];"
                 : "=r"(r[0]), "=r"(r[1]), "=r"(r[2]), "=r"(r[3]) : "r"(addr));
}
__device__ __forceinline__ void mma16816(float* c, const uint32_t* a,
                                         uint32_t b0, uint32_t b1) {
    asm volatile("mma.sync.aligned.m16n8k16.row.col.f32.f16.f16.f32 "
        "{%0,%1,%2,%3}, {%4,%5,%6,%7}, {%8,%9}, {%0,%1,%2,%3};"
        : "+f"(c[0]), "+f"(c[1]), "+f"(c[2]), "+f"(c[3])
        : "r"(a[0]), "r"(a[1]), "r"(a[2]), "r"(a[3]), "r"(b0), "r"(b1));
}

// ================= merged weight transpose (fp16, no split) ================
struct PrepJobs {
    const float* W[8];
    fp16* T[8];
    int K[8], N[8], cum[9];
};
__global__ __launch_bounds__(256) void prep_all_kernel(PrepJobs pj)
{
    int bx = blockIdx.x, j = 0;
    #pragma unroll
    for (int i = 0; i < 8; i++) if (bx >= pj.cum[i + 1]) j = i + 1;
    const int local = bx - pj.cum[j];
    const int K = pj.K[j], N = pj.N[j];
    const int nbn = N / 32;
    const int n0 = (local % nbn) * 32, k0 = (local / nbn) * 32;
    const float* W = pj.W[j];
    fp16* T = pj.T[j];

    __shared__ float tile[32][33];
    int tx = threadIdx.x & 31, ty = threadIdx.x >> 5;
    for (int r = ty; r < 32; r += 8)
        tile[r][tx] = W[(size_t)(k0 + r) * N + n0 + tx];
    __syncthreads();
    for (int r = ty; r < 32; r += 8)
        T[(size_t)(n0 + r) * K + k0 + tx] = __float2half(tile[tx][r]);
}

__global__ __launch_bounds__(256) void bias_prep_kernel(
    const float* __restrict__ bl, const float* __restrict__ br)
{
    int idx = blockIdx.x * 256 + threadIdx.x;
    if (idx < 2560)
        g_bias_lr[idx] = (idx < PP) ? bl[idx] : br[idx - PP];
}

// ================= layernorm + fp16 split ==================================
__global__ __launch_bounds__(256) void ln_split_kernel(
    const float* __restrict__ x, const float* __restrict__ w,
    const float* __restrict__ b, fp16* __restrict__ oh, fp16* __restrict__ ol)
{
    int t = blockIdx.x;
    const float* row = x + (size_t)t * DD;
    float s = 0.f, s2 = 0.f;
    for (int i = threadIdx.x; i < DD; i += 256) {
        float v = row[i]; s += v; s2 += v * v;
    }
    __shared__ float sh[16];
    int warp = threadIdx.x >> 5, lane = threadIdx.x & 31;
    #pragma unroll
    for (int o = 16; o; o >>= 1) {
        s  += __shfl_xor_sync(0xffffffffu, s,  o);
        s2 += __shfl_xor_sync(0xffffffffu, s2, o);
    }
    if (lane == 0) { sh[warp] = s; sh[8 + warp] = s2; }
    __syncthreads();
    if (threadIdx.x == 0) {
        float ts = 0.f, ts2 = 0.f;
        #pragma unroll
        for (int i = 0; i < 8; i++) { ts += sh[i]; ts2 += sh[8 + i]; }
        float mu  = ts  * (1.f / DD);
        float var = ts2 * (1.f / DD) - mu * mu;
        sh[0] = mu; sh[1] = rsqrtf(var + 1e-6f);
    }
    __syncthreads();
    float mu = sh[0], rstd = sh[1];
    for (int i = threadIdx.x; i < DD; i += 256) {
        float y = (row[i] - mu) * rstd * w[i] + b[i];
        split_store(y, oh, ol, (size_t)t * DD + i);
    }
}

// ============ mma.sync fp16 2-pass GEMM (BK=32, 3-stage, 2 CTAs/SM) ========
// D = (Ah + Al) @ B + bias.  Ah/Al fp16 activation split, B fp16 weights.
struct GemmJob {
    const fp16 *Ah, *Al, *B;
    const float *bias, *res;
    float *out;
    fp16 *oh, *ol;
    float *out2;                  // columns >= ncut go here (ld = ldo2)
    int ncut, ldo, ldo2;
};
struct GemmParams { GemmJob jobs[5]; int K; };

#define PADK 40                        // halves per smem row (32 + 8 pad)
#define OPT  (128*PADK)                // halves per operand tile
#define STG3 (3*OPT)                   // halves per stage (Ah, Al, B)
#define GSMEM_BYTES (3*STG3*2)         // 92160 B -> 2 CTAs/SM

__global__ __launch_bounds__(256, 2) void gemm_mma_kernel(GemmParams p)
{
    const GemmJob J = p.jobs[blockIdx.z];
    const int bm = blockIdx.y * 128, bn = blockIdx.x * 128;

    extern __shared__ fp16 smg[];
    const uint32_t sbase = smem_u32(smg);
    const int K = p.K;
    const int tid = threadIdx.x, lane = tid & 31, wid = tid >> 5;
    const int warpM = wid & 3, warpN = wid >> 2;    // 4 x 2 warps, tile 32x64

    const fp16* gsrc[3];
    gsrc[0] = J.Ah + (size_t)bm * K;
    gsrc[1] = J.Al + (size_t)bm * K;
    gsrc[2] = J.B  + (size_t)bn * K;

    const int lrow = tid >> 1;
    const int lcol = (tid & 1) * 16;   // halves
    const uint32_t swr = sbase + (uint32_t)(lrow * PADK + lcol) * 2;

    float acc[2][8][4];
    #pragma unroll
    for (int i = 0; i < 2; i++)
        #pragma unroll
        for (int j = 0; j < 8; j++)
            #pragma unroll
            for (int e = 0; e < 4; e++) acc[i][j][e] = 0.f;

    const int NT = K / 32;

    // preload stages 0, 1
    #pragma unroll
    for (int s = 0; s < 2; s++) {
        #pragma unroll
        for (int w = 0; w < 3; w++) {
            const fp16* g = gsrc[w] + (size_t)lrow * K + s * 32 + lcol;
            uint32_t sa = swr + (uint32_t)(s * STG3 + w * OPT) * 2;
            cp16(sa, g); cp16(sa + 16, g + 8);
        }
        asm volatile("cp.async.commit_group;");
    }

    for (int kt = 0; kt < NT; kt++) {
        if (kt < NT - 1) asm volatile("cp.async.wait_group 1;");
        else             asm volatile("cp.async.wait_group 0;");
        __syncthreads();

        // prefetch kt+2 (overlaps with compute below)
        if (kt + 2 < NT) {
            const int s = (kt + 2) % 3;
            const int k0 = (kt + 2) * 32;
            #pragma unroll
            for (int w = 0; w < 3; w++) {
                const fp16* g = gsrc[w] + (size_t)lrow * K + k0 + lcol;
                uint32_t sa = swr + (uint32_t)(s * STG3 + w * OPT) * 2;
                cp16(sa, g); cp16(sa + 16, g + 8);
            }
            asm volatile("cp.async.commit_group;");
        }

        const uint32_t stg = sbase + (uint32_t)((kt % 3) * STG3) * 2;
        #pragma unroll
        for (int ks = 0; ks < 2; ks++) {
            const int koff = ks * 16 + ((lane >> 4) << 3);
            const int rsel = lane & 15;
            uint32_t a[2][2][4], b[4][4];
            #pragma unroll
            for (int op = 0; op < 2; op++)
                #pragma unroll
                for (int i = 0; i < 2; i++) {
                    const int row = warpM * 32 + i * 16 + rsel;
                    ldm4(stg + (uint32_t)(op * OPT + row * PADK + koff) * 2,
                         a[op][i]);
                }
            #pragma unroll
            for (int j = 0; j < 4; j++) {
                const int row = warpN * 64 + j * 16 + rsel;
                ldm4(stg + (uint32_t)(2 * OPT + row * PADK + koff) * 2, b[j]);
            }
            #pragma unroll
            for (int op = 0; op < 2; op++)
                #pragma unroll
                for (int i = 0; i < 2; i++)
                    #pragma unroll
                    for (int j = 0; j < 8; j++)
                        mma16816(acc[i][j], a[op][i],
                                 b[j >> 1][j & 1], b[j >> 1][(j & 1) + 2]);
        }
    }

    const int er = (lane >> 2);
    const int ec = (lane & 3) * 2;
    #pragma unroll
    for (int i = 0; i < 2; i++) {
        #pragma unroll
        for (int j = 0; j < 8; j++) {
            const int row0 = bm + warpM * 32 + i * 16 + er;
            const int col0 = bn + warpN * 64 + j * 8 + ec;
            #pragma unroll
            for (int e = 0; e < 4; e++) {
                const int row = row0 + (e >> 1) * 8;
                const int col = col0 + (e & 1);
                float v = acc[i][j][e] + J.bias[col];
                if (col >= J.ncut) {
                    J.out2[(size_t)row * J.ldo2 + (col - J.ncut)] = v;
                } else {
                    if (J.res) v += J.res[(size_t)row * J.ldo + col];
                    const size_t idx = (size_t)row * J.ldo + col;
                    J.out[idx] = v;
                    if (J.oh) split_store(v, J.oh, J.ol, idx);
                }
            }
        }
    }
}

// ================= causal feature-conv + silu + split ======================
__global__ __launch_bounds__(256) void conv_silu_kernel(
    const float* __restrict__ xt, const float* __restrict__ cw,
    const float* __restrict__ cbp, float* __restrict__ xc,
    fp16* __restrict__ xch, fp16* __restrict__ xcl)
{
    int t = blockIdx.x;
    int pcol = blockIdx.y * 256 + threadIdx.x;
    const float* row = xt + (size_t)t * PP;
    float w0 = cw[0], w1 = cw[1], w2 = cw[2], w3 = cw[3];
    float acc = row[pcol] * w3;
    if (pcol >= 1) acc += row[pcol - 1] * w2;
    if (pcol >= 2) acc += row[pcol - 2] * w1;
    if (pcol >= 3) acc += row[pcol - 3] * w0;
    acc += cbp[0];
    float y = acc / (1.f + expf(-acc));
    size_t idx = (size_t)t * PP + pcol;
    xc[idx] = y;
    split_store(y, xch, xcl, idx);
}

// ================= i/f gates (fp32 — precision-critical path) ==============
__global__ __launch_bounds__(256) void gates_kernel(
    const float* __restrict__ xc,
    const float* __restrict__ Wi, const float* __restrict__ bi,
    const float* __restrict__ Wf, const float* __restrict__ bf_,
    float* __restrict__ gi, float* __restrict__ gf)
{
    int t = blockIdx.x;
    int warp = threadIdx.x >> 5, lane = threadIdx.x & 31;
    const float* row = xc + (size_t)t * PP;
    float si = 0.f, sf = 0.f;
    for (int p = lane; p < PP; p += 32) {
        float xv = row[p];
        si += xv * Wi[p * HH + warp];
        sf += xv * Wf[p * HH + warp];
    }
    #pragma unroll
    for (int o = 16; o; o >>= 1) {
        si += __shfl_xor_sync(0xffffffffu, si, o);
        sf += __shfl_xor_sync(0xffffffffu, sf, o);
    }
    if (lane == 0) {
        float a  = si + bi[warp];
        float b2 = sf + bf_[warp];
        gi[t * HH + warp] = 15.f * tanhf(a  * (1.f / 15.f));
        gf[t * HH + warp] = 15.f * tanhf(b2 * (1.f / 15.f));
    }
}

// ================= gate prefix scans (exact linearization) =================
__global__ __launch_bounds__(TT) void gatescan_kernel(
    const float* __restrict__ gi, const float* __restrict__ gf,
    float* __restrict__ a_out, float* __restrict__ M_out)
{
    const int bh = blockIdx.x;          // b*HH + h
    const int b = bh >> 3, h = bh & 7;
    const int t = threadIdx.x;
    __shared__ float sf[TT], sa[TT];
    const int gidx = (b * TT + t) * HH + h;
    sf[t] = gf[gidx];
    const float iv = gi[gidx];
    __syncthreads();
    #pragma unroll
    for (int st = 1; st < TT; st <<= 1) {
        float add = (t >= st) ? sf[t - st] : 0.f;
        __syncthreads();
        sf[t] += add;
        __syncthreads();
    }
    const float a = iv - sf[t];
    a_out[bh * TT + t] = a;
    sa[t] = a;
    __syncthreads();
    #pragma unroll
    for (int st = 1; st < TT; st <<= 1) {
        float mx = (t >= st) ? sa[t - st] : -3.4e38f;
        __syncthreads();
        sa[t] = fmaxf(sa[t], mx);
        __syncthreads();
    }
    M_out[bh * TT + t] = fmaxf(0.f, sa[t]);
}

// ================= parallel attention-form scan ============================
#define QT 64
#define AP 68                       // row pad (floats); 272B, 16B aligned
#define ASM_BYTES ((4*QT*AP + QT) * 4)

__global__ __launch_bounds__(256) void attn_kernel(
    const float* __restrict__ q, const float* __restrict__ kraw,
    const float* __restrict__ v, const float* __restrict__ aex,
    const float* __restrict__ Mex, const float* __restrict__ oraw,
    const float* __restrict__ skip, const float* __restrict__ rraw,
    const float* __restrict__ hlnw, const float* __restrict__ hlnb,
    fp16* __restrict__ outh, fp16* __restrict__ outl)
{
    const int bh = blockIdx.y, b = bh >> 3, h = bh & 7;
    const int t0 = blockIdx.x * QT;
    extern __shared__ float sm[];
    float* ks = sm;                  // [64][AP]
    float* vs = ks + QT * AP;
    float* qs = vs + QT * AP;
    float* ss = qs + QT * AP;
    float* as_ = ss + QT * AP;       // [64]

    const int tid = threadIdx.x;
    const int qi = tid >> 2, sub = tid & 3;
    const int tq = t0 + qi;
    const size_t qbase = (size_t)(b * TT + tq) * HD + h * DH;

    {
        const int lr = tid >> 2, lc = (tid & 3) * 16;
        const float* src = q + (size_t)(b * TT + t0 + lr) * HD + h * DH + lc;
        #pragma unroll
        for (int i = 0; i < 16; i += 4)
            *(float4*)&qs[lr * AP + lc + i] = *(const float4*)(src + i);
    }
    __syncthreads();

    const float Mt = Mex[bh * TT + tq];
    float num[16];
    #pragma unroll
    for (int i = 0; i < 16; i++) num[i] = 0.f;
    float den = 0.f;

    for (int j0 = 0; j0 <= t0; j0 += QT) {
        {
            const int lr = tid >> 2, lc = (tid & 3) * 16;
            const size_t gb = (size_t)(b * TT + j0 + lr) * HD + h * DH + lc;
            #pragma unroll
            for (int i = 0; i < 16; i += 4) {
                *(float4*)&ks[lr * AP + lc + i] = *(const float4*)(kraw + gb + i);
                *(float4*)&vs[lr * AP + lc + i] = *(const float4*)(v + gb + i);
            }
            if (tid < QT) as_[tid] = aex[bh * TT + j0 + tid];
        }
        __syncthreads();

        float sc[16];
        #pragma unroll
        for (int jj = 0; jj < 16; jj++) sc[jj] = 0.f;
        const float* qrow = &qs[qi * AP];
        #pragma unroll 4
        for (int d = 0; d < DH; d += 4) {
            float q0 = qrow[d], q1 = qrow[d+1], q2 = qrow[d+2], q3 = qrow[d+3];
            #pragma unroll
            for (int jj = 0; jj < 16; jj++) {
                const float* kr = &ks[(sub + 4*jj) * AP + d];
                sc[jj] += q0*kr[0] + q1*kr[1] + q2*kr[2] + q3*kr[3];
            }
        }
        const bool diag = (j0 == t0);
        #pragma unroll
        for (int jj = 0; jj < 16; jj++) {
            const int j = sub + 4*jj;
            float w = (diag && j > qi) ? 0.f
                      : __expf(as_[j] - Mt) * 0.125f * sc[jj];
            ss[qi * AP + j] = w;
            den += w;
        }
        __syncthreads();

        #pragma unroll 8
        for (int j = 0; j < QT; j++) {
            const float s = ss[qi * AP + j];
            const float* vr = &vs[j * AP + sub];
            #pragma unroll
            for (int dd = 0; dd < 16; dd++)
                num[dd] += s * vr[4*dd];
        }
        __syncthreads();
    }

    float sumq = 0.f;
    #pragma unroll
    for (int dd = 0; dd < 16; dd++) sumq += qs[qi * AP + sub + 4*dd];
    den  += __shfl_xor_sync(0xffffffffu, den, 1);
    den  += __shfl_xor_sync(0xffffffffu, den, 2);
    sumq += __shfl_xor_sync(0xffffffffu, sumq, 1);
    sumq += __shfl_xor_sync(0xffffffffu, sumq, 2);
    den = fmaxf(den + __expf(-Mt) * sumq, 1.0f);
    const float rden = 1.f / den;

    float hh[16], s1 = 0.f, s2 = 0.f;
    #pragma unroll
    for (int dd = 0; dd < 16; dd++) {
        const int d = sub + 4*dd;
        const float ov = oraw[qbase + d];
        const float og = 1.f / (1.f + __expf(-ov));
        const float hv = og * num[dd] * rden;
        hh[dd] = hv;
        s1 += hv; s2 += hv * hv;
    }
    s1 += __shfl_xor_sync(0xffffffffu, s1, 1);
    s1 += __shfl_xor_sync(0xffffffffu, s1, 2);
    s2 += __shfl_xor_sync(0xffffffffu, s2, 1);
    s2 += __shfl_xor_sync(0xffffffffu, s2, 2);
    const float mu  = s1 * (1.f / DH);
    const float var = s2 * (1.f / DH) - mu * mu;
    const float rstd = rsqrtf(var + 1e-6f);
    #pragma unroll
    for (int dd = 0; dd < 16; dd++) {
        const int d = sub + 4*dd;
        const float hn = (hh[dd] - mu) * rstd * hlnw[h*DH + d] + hlnb[h*DH + d];
        const float rv = rraw[qbase + d];
        const float sil = rv / (1.f + __expf(-rv));
        const float val = (hn + skip[qbase + d]) * sil;
        split_store(val, outh, outl, qbase + d);
    }
}

// ===========================================================================
extern "C" void kernel_launch(void* const* d_in, const int* in_sizes, int n_in,
                              void* d_out, int out_size)
{
    const float* x      = (const float*)d_in[0];
    const float* ln_w   = (const float*)d_in[1];
    const float* ln_b   = (const float*)d_in[2];
    const float* hln_w  = (const float*)d_in[3];
    const float* hln_b  = (const float*)d_in[4];
    const float* Wl     = (const float*)d_in[5];
    const float* bl     = (const float*)d_in[6];
    const float* Wr     = (const float*)d_in[7];
    const float* br     = (const float*)d_in[8];
    const float* conv_w = (const float*)d_in[9];
    const float* conv_b = (const float*)d_in[10];
    const float* Wskip  = (const float*)d_in[11];
    const float* bskip  = (const float*)d_in[12];
    const float* Wi     = (const float*)d_in[13];
    const float* bi     = (const float*)d_in[14];
    const float* Wf     = (const float*)d_in[15];
    const float* bf_    = (const float*)d_in[16];
    const float* Wo     = (const float*)d_in[17];
    const float* bo     = (const float*)d_in[18];
    const float* Wq     = (const float*)d_in[19];
    const float* bq     = (const float*)d_in[20];
    const float* Wk     = (const float*)d_in[21];
    const float* bk     = (const float*)d_in[22];
    const float* Wv     = (const float*)d_in[23];
    const float* bv     = (const float*)d_in[24];
    const float* Wd     = (const float*)d_in[25];
    const float* bd     = (const float*)d_in[26];
    float* out = (float*)d_out;

    fp16 *xn_h, *xn_l, *xt_h, *xt_l, *xc_h, *xc_l, *cm_h, *cm_l;
    fp16 *WlrT, *WsT, *WqT, *WkT, *WvT, *WoT, *WdT;
    float *xt, *xc, *r, *skip, *q, *k, *v, *o, *gi, *gf, *aex, *Mex, *bias_lr;
    cudaGetSymbolAddress((void**)&xn_h, g_xn_h);  cudaGetSymbolAddress((void**)&xn_l, g_xn_l);
    cudaGetSymbolAddress((void**)&xt,   g_xt);
    cudaGetSymbolAddress((void**)&xt_h, g_xt_h);  cudaGetSymbolAddress((void**)&xt_l, g_xt_l);
    cudaGetSymbolAddress((void**)&xc,   g_xc);
    cudaGetSymbolAddress((void**)&xc_h, g_xc_h);  cudaGetSymbolAddress((void**)&xc_l, g_xc_l);
    cudaGetSymbolAddress((void**)&r,    g_r);     cudaGetSymbolAddress((void**)&skip, g_skip);
    cudaGetSymbolAddress((void**)&q,    g_q);     cudaGetSymbolAddress((void**)&k,    g_k);
    cudaGetSymbolAddress((void**)&v,    g_v);     cudaGetSymbolAddress((void**)&o,    g_o);
    cudaGetSymbolAddress((void**)&gi,   g_ig);    cudaGetSymbolAddress((void**)&gf,   g_fg);
    cudaGetSymbolAddress((void**)&aex,  g_a);     cudaGetSymbolAddress((void**)&Mex,  g_M);
    cudaGetSymbolAddress((void**)&cm_h, g_cm_h);  cudaGetSymbolAddress((void**)&cm_l, g_cm_l);
    cudaGetSymbolAddress((void**)&WlrT, g_WlrT);
    cudaGetSymbolAddress((void**)&WsT,  g_WsT);   cudaGetSymbolAddress((void**)&WqT,  g_WqT);
    cudaGetSymbolAddress((void**)&WkT,  g_WkT);   cudaGetSymbolAddress((void**)&WvT,  g_WvT);
    cudaGetSymbolAddress((void**)&WoT,  g_WoT);   cudaGetSymbolAddress((void**)&WdT,  g_WdT);
    cudaGetSymbolAddress((void**)&bias_lr, g_bias_lr);

    cudaFuncSetAttribute(gemm_mma_kernel,
                         cudaFuncAttributeMaxDynamicSharedMemorySize, GSMEM_BYTES);
    cudaFuncSetAttribute(attn_kernel,
                         cudaFuncAttributeMaxDynamicSharedMemorySize, ASM_BYTES);

    // 1. merged weight prep (8 transpose jobs in one launch)
    {
        PrepJobs pj{};
        const float* Ws[8] = { Wl, Wr, Wskip, Wq, Wk, Wv, Wo, Wd };
        fp16* Ts[8] = { WlrT, WlrT + (size_t)PP * DD, WsT, WqT, WkT, WvT, WoT, WdT };
        int Ks[8] = { DD, DD, PP, PP, PP, PP, PP, HD };
        int Ns[8] = { PP, HD, HD, HD, HD, HD, HD, DD };
        int cum = 0;
        for (int i = 0; i < 8; i++) {
            pj.W[i] = Ws[i]; pj.T[i] = Ts[i];
            pj.K[i] = Ks[i]; pj.N[i] = Ns[i];
            pj.cum[i] = cum;
            cum += (Ns[i] / 32) * (Ks[i] / 32);
        }
        pj.cum[8] = cum;
        prep_all_kernel<<<cum, 256>>>(pj);
    }
    bias_prep_kernel<<<10, 256>>>(bl, br);

    // 2. layernorm -> xn splits
    ln_split_kernel<<<NTOK, 256>>>(x, ln_w, ln_b, xn_h, xn_l);

    // 3. merged [xt | r] = xn @ [Wl | Wr] + [bl | br]
    {
        GemmParams p{}; p.K = DD;
        p.jobs[0] = { xn_h, xn_l, WlrT, bias_lr, nullptr,
                      xt, xt_h, xt_l, r, PP, PP, HD };
        gemm_mma_kernel<<<dim3(2560/128, NTOK/128, 1), 256, GSMEM_BYTES>>>(p);
    }
    // 4. conv + silu -> xc
    conv_silu_kernel<<<dim3(NTOK, PP/256), 256>>>(xt, conv_w, conv_b, xc, xc_h, xc_l);

    // 5. five P->HD projections in one batched launch
    {
        const int NC = 1 << 30;
        GemmParams p{}; p.K = PP;
        p.jobs[0] = { xc_h, xc_l, WsT, bskip, nullptr, skip, nullptr, nullptr, nullptr, NC, HD, 0 };
        p.jobs[1] = { xc_h, xc_l, WqT, bq,    nullptr, q,    nullptr, nullptr, nullptr, NC, HD, 0 };
        p.jobs[2] = { xc_h, xc_l, WkT, bk,    nullptr, k,    nullptr, nullptr, nullptr, NC, HD, 0 };
        p.jobs[3] = { xt_h, xt_l, WvT, bv,    nullptr, v,    nullptr, nullptr, nullptr, NC, HD, 0 };
        p.jobs[4] = { xt_h, xt_l, WoT, bo,    nullptr, o,    nullptr, nullptr, nullptr, NC, HD, 0 };
        gemm_mma_kernel<<<dim3(HD/128, NTOK/128, 5), 256, GSMEM_BYTES>>>(p);
    }
    // 6. i/f gates (fp32) + prefix scans
    gates_kernel<<<NTOK, 256>>>(xc, Wi, bi, Wf, bf_, gi, gf);
    gatescan_kernel<<<BB*HH, TT>>>(gi, gf, aex, Mex);

    // 7. parallel attention-form scan -> comb splits
    attn_kernel<<<dim3(TT/QT, BB*HH), 256, ASM_BYTES>>>(
        q, k, v, aex, Mex, o, skip, r, hln_w, hln_b, cm_h, cm_l);

    // 8. out = comb @ Wd + bd + x
    {
        const int NC = 1 << 30;
        GemmParams p{}; p.K = HD;
        p.jobs[0] = { cm_h, cm_l, WdT, bd, x, out, nullptr, nullptr, nullptr, NC, DD, 0 };
        gemm_mma_kernel<<<dim3(DD/128, NTOK/128, 1), 256, GSMEM_BYTES>>>(p);
    }
}

// round 11
// speedup vs baseline: 1.7884x; 1.2848x over previous
#include <cuda_runtime.h>
#include <cuda_fp16.h>
#include <cstdint>
#include <math.h>

typedef __half fp16;

// Problem constants
#define BB 4
#define TT 512
#define DD 1024
#define HH 8
#define DH 64
#define HD 512
#define PP 2048
#define NTOK (BB*TT)          // 2048 tokens

// ================= scratch (device globals) =================================
__device__ fp16  g_xn16[NTOK*DD];
__device__ float g_xt  [NTOK*PP];
__device__ fp16  g_xt16[NTOK*PP];
__device__ float g_xc  [NTOK*PP];
__device__ fp16  g_xc16[NTOK*PP];
__device__ float g_r   [NTOK*HD], g_skip[NTOK*HD];
__device__ float g_q   [NTOK*HD], g_k   [NTOK*HD];
__device__ float g_v   [NTOK*HD], g_o   [NTOK*HD];
__device__ float g_ig  [NTOK*HH], g_fg  [NTOK*HH];
__device__ float g_a   [BB*HH*TT], g_M [BB*HH*TT];
__device__ fp16  g_cm16[NTOK*HD];
// transposed weights (fp16): WT[N,K]
__device__ fp16 g_WlrT[2560*DD];      // [Wl | Wr] cols, K=1024
__device__ fp16 g_WsT[HD*PP], g_WqT[HD*PP], g_WkT[HD*PP];
__device__ fp16 g_WvT[HD*PP], g_WoT[HD*PP], g_WdT[DD*HD];
__device__ float g_bias_lr[2560];

__device__ __forceinline__ uint32_t smem_u32(const void* p) {
    uint32_t a;
    asm("{ .reg .u64 t; cvta.to.shared.u64 t, %1; cvt.u32.u64 %0, t; }"
        : "=r"(a) : "l"(p));
    return a;
}
__device__ __forceinline__ void cp16(uint32_t s, const void* g) {
    asm volatile("cp.async.cg.shared.global [%0], [%1], 16;" :: "r"(s), "l"(g));
}
__device__ __forceinline__ void ldm4(uint32_t addr, uint32_t* r) {
    asm volatile("ldmatrix.sync.aligned.m8n8.x4.shared.b16 {%0,%1,%2,%3}, [%4];"
                 : "=r"(r[0]), "=r"(r[1]), "=r"(r[2]), "=r"(r[3]) : "r"(addr));
}
__device__ __forceinline__ void mma16816(float* c, const uint32_t* a,
                                         uint32_t b0, uint32_t b1) {
    asm volatile("mma.sync.aligned.m16n8k16.row.col.f32.f16.f16.f32 "
        "{%0,%1,%2,%3}, {%4,%5,%6,%7}, {%8,%9}, {%0,%1,%2,%3};"
        : "+f"(c[0]), "+f"(c[1]), "+f"(c[2]), "+f"(c[3])
        : "r"(a[0]), "r"(a[1]), "r"(a[2]), "r"(a[3]), "r"(b0), "r"(b1));
}

// ================= merged weight transpose (fp16) ==========================
struct PrepJobs {
    const float* W[8];
    fp16* T[8];
    int K[8], N[8], cum[9];
};
__global__ __launch_bounds__(256) void prep_all_kernel(PrepJobs pj)
{
    int bx = blockIdx.x, j = 0;
    #pragma unroll
    for (int i = 0; i < 8; i++) if (bx >= pj.cum[i + 1]) j = i + 1;
    const int local = bx - pj.cum[j];
    const int K = pj.K[j], N = pj.N[j];
    const int nbn = N / 32;
    const int n0 = (local % nbn) * 32, k0 = (local / nbn) * 32;
    const float* W = pj.W[j];
    fp16* T = pj.T[j];

    __shared__ float tile[32][33];
    int tx = threadIdx.x & 31, ty = threadIdx.x >> 5;
    for (int r = ty; r < 32; r += 8)
        tile[r][tx] = W[(size_t)(k0 + r) * N + n0 + tx];
    __syncthreads();
    for (int r = ty; r < 32; r += 8)
        T[(size_t)(n0 + r) * K + k0 + tx] = __float2half(tile[tx][r]);
}

__global__ __launch_bounds__(256) void bias_prep_kernel(
    const float* __restrict__ bl, const float* __restrict__ br)
{
    int idx = blockIdx.x * 256 + threadIdx.x;
    if (idx < 2560)
        g_bias_lr[idx] = (idx < PP) ? bl[idx] : br[idx - PP];
}

// ================= layernorm -> fp16 =======================================
__global__ __launch_bounds__(256) void ln_kernel(
    const float* __restrict__ x, const float* __restrict__ w,
    const float* __restrict__ b, fp16* __restrict__ o16)
{
    int t = blockIdx.x;
    const float* row = x + (size_t)t * DD;
    float s = 0.f, s2 = 0.f;
    for (int i = threadIdx.x; i < DD; i += 256) {
        float v = row[i]; s += v; s2 += v * v;
    }
    __shared__ float sh[16];
    int warp = threadIdx.x >> 5, lane = threadIdx.x & 31;
    #pragma unroll
    for (int o = 16; o; o >>= 1) {
        s  += __shfl_xor_sync(0xffffffffu, s,  o);
        s2 += __shfl_xor_sync(0xffffffffu, s2, o);
    }
    if (lane == 0) { sh[warp] = s; sh[8 + warp] = s2; }
    __syncthreads();
    if (threadIdx.x == 0) {
        float ts = 0.f, ts2 = 0.f;
        #pragma unroll
        for (int i = 0; i < 8; i++) { ts += sh[i]; ts2 += sh[8 + i]; }
        float mu  = ts  * (1.f / DD);
        float var = ts2 * (1.f / DD) - mu * mu;
        sh[0] = mu; sh[1] = rsqrtf(var + 1e-6f);
    }
    __syncthreads();
    float mu = sh[0], rstd = sh[1];
    for (int i = threadIdx.x; i < DD; i += 256)
        o16[(size_t)t * DD + i] = __float2half((row[i] - mu) * rstd * w[i] + b[i]);
}

// ============ mma.sync fp16 single-pass GEMM (BK=32, 3-stage) ==============
struct GemmJob {
    const fp16 *A, *B;
    const float *bias, *res;
    float *out;
    fp16 *o16;
    float *out2;                  // columns >= ncut go here (ld = ldo2)
    int ncut, ldo, ldo2;
};
struct GemmParams { GemmJob jobs[5]; int K; };

#define PADK 40                        // halves per smem row (32 + 8 pad)
#define OPT  (128*PADK)                // halves per operand tile
#define STG2 (2*OPT)                   // halves per stage (A, B)
#define GSMEM_BYTES (3*STG2*2)         // 61440 B

__global__ __launch_bounds__(256, 2) void gemm_mma_kernel(GemmParams p)
{
    const GemmJob J = p.jobs[blockIdx.z];
    const int bm = blockIdx.y * 128, bn = blockIdx.x * 128;

    extern __shared__ fp16 smg[];
    const uint32_t sbase = smem_u32(smg);
    const int K = p.K;
    const int tid = threadIdx.x, lane = tid & 31, wid = tid >> 5;
    const int warpM = wid & 3, warpN = wid >> 2;    // 4 x 2 warps, tile 32x64

    const fp16* gsrc[2];
    gsrc[0] = J.A + (size_t)bm * K;
    gsrc[1] = J.B + (size_t)bn * K;

    const int lrow = tid >> 1;
    const int lcol = (tid & 1) * 16;   // halves
    const uint32_t swr = sbase + (uint32_t)(lrow * PADK + lcol) * 2;

    float acc[2][8][4];
    #pragma unroll
    for (int i = 0; i < 2; i++)
        #pragma unroll
        for (int j = 0; j < 8; j++)
            #pragma unroll
            for (int e = 0; e < 4; e++) acc[i][j][e] = 0.f;

    const int NT = K / 32;

    // preload stages 0, 1
    #pragma unroll
    for (int s = 0; s < 2; s++) {
        #pragma unroll
        for (int w = 0; w < 2; w++) {
            const fp16* g = gsrc[w] + (size_t)lrow * K + s * 32 + lcol;
            uint32_t sa = swr + (uint32_t)(s * STG2 + w * OPT) * 2;
            cp16(sa, g); cp16(sa + 16, g + 8);
        }
        asm volatile("cp.async.commit_group;");
    }

    for (int kt = 0; kt < NT; kt++) {
        if (kt < NT - 1) asm volatile("cp.async.wait_group 1;");
        else             asm volatile("cp.async.wait_group 0;");
        __syncthreads();

        // prefetch kt+2 (overlaps with compute below)
        if (kt + 2 < NT) {
            const int s = (kt + 2) % 3;
            const int k0 = (kt + 2) * 32;
            #pragma unroll
            for (int w = 0; w < 2; w++) {
                const fp16* g = gsrc[w] + (size_t)lrow * K + k0 + lcol;
                uint32_t sa = swr + (uint32_t)(s * STG2 + w * OPT) * 2;
                cp16(sa, g); cp16(sa + 16, g + 8);
            }
            asm volatile("cp.async.commit_group;");
        }

        const uint32_t stg = sbase + (uint32_t)((kt % 3) * STG2) * 2;
        #pragma unroll
        for (int ks = 0; ks < 2; ks++) {
            const int koff = ks * 16 + ((lane >> 4) << 3);
            const int rsel = lane & 15;
            uint32_t a[2][4], b[4][4];
            #pragma unroll
            for (int i = 0; i < 2; i++) {
                const int row = warpM * 32 + i * 16 + rsel;
                ldm4(stg + (uint32_t)(row * PADK + koff) * 2, a[i]);
            }
            #pragma unroll
            for (int j = 0; j < 4; j++) {
                const int row = warpN * 64 + j * 16 + rsel;
                ldm4(stg + (uint32_t)(OPT + row * PADK + koff) * 2, b[j]);
            }
            #pragma unroll
            for (int i = 0; i < 2; i++)
                #pragma unroll
                for (int j = 0; j < 8; j++)
                    mma16816(acc[i][j], a[i],
                             b[j >> 1][j & 1], b[j >> 1][(j & 1) + 2]);
        }
    }

    const int er = (lane >> 2);
    const int ec = (lane & 3) * 2;
    #pragma unroll
    for (int i = 0; i < 2; i++) {
        #pragma unroll
        for (int j = 0; j < 8; j++) {
            const int row0 = bm + warpM * 32 + i * 16 + er;
            const int col0 = bn + warpN * 64 + j * 8 + ec;
            #pragma unroll
            for (int e = 0; e < 4; e++) {
                const int row = row0 + (e >> 1) * 8;
                const int col = col0 + (e & 1);
                float v = acc[i][j][e] + J.bias[col];
                if (col >= J.ncut) {
                    J.out2[(size_t)row * J.ldo2 + (col - J.ncut)] = v;
                } else {
                    if (J.res) v += J.res[(size_t)row * J.ldo + col];
                    const size_t idx = (size_t)row * J.ldo + col;
                    J.out[idx] = v;
                    if (J.o16) J.o16[idx] = __float2half(v);
                }
            }
        }
    }
}

// ================= causal feature-conv + silu ==============================
__global__ __launch_bounds__(256) void conv_silu_kernel(
    const float* __restrict__ xt, const float* __restrict__ cw,
    const float* __restrict__ cbp, float* __restrict__ xc,
    fp16* __restrict__ xc16)
{
    int t = blockIdx.x;
    int pcol = blockIdx.y * 256 + threadIdx.x;
    const float* row = xt + (size_t)t * PP;
    float w0 = cw[0], w1 = cw[1], w2 = cw[2], w3 = cw[3];
    float acc = row[pcol] * w3;
    if (pcol >= 1) acc += row[pcol - 1] * w2;
    if (pcol >= 2) acc += row[pcol - 2] * w1;
    if (pcol >= 3) acc += row[pcol - 3] * w0;
    acc += cbp[0];
    float y = acc / (1.f + expf(-acc));
    size_t idx = (size_t)t * PP + pcol;
    xc[idx] = y;
    xc16[idx] = __float2half(y);
}

// ================= i/f gates (fp32 — precision-critical path) ==============
__global__ __launch_bounds__(256) void gates_kernel(
    const float* __restrict__ xc,
    const float* __restrict__ Wi, const float* __restrict__ bi,
    const float* __restrict__ Wf, const float* __restrict__ bf_,
    float* __restrict__ gi, float* __restrict__ gf)
{
    int t = blockIdx.x;
    int warp = threadIdx.x >> 5, lane = threadIdx.x & 31;
    const float* row = xc + (size_t)t * PP;
    float si = 0.f, sf = 0.f;
    for (int p = lane; p < PP; p += 32) {
        float xv = row[p];
        si += xv * Wi[p * HH + warp];
        sf += xv * Wf[p * HH + warp];
    }
    #pragma unroll
    for (int o = 16; o; o >>= 1) {
        si += __shfl_xor_sync(0xffffffffu, si, o);
        sf += __shfl_xor_sync(0xffffffffu, sf, o);
    }
    if (lane == 0) {
        float a  = si + bi[warp];
        float b2 = sf + bf_[warp];
        gi[t * HH + warp] = 15.f * tanhf(a  * (1.f / 15.f));
        gf[t * HH + warp] = 15.f * tanhf(b2 * (1.f / 15.f));
    }
}

// ================= gate prefix scans (exact linearization) =================
__global__ __launch_bounds__(TT) void gatescan_kernel(
    const float* __restrict__ gi, const float* __restrict__ gf,
    float* __restrict__ a_out, float* __restrict__ M_out)
{
    const int bh = blockIdx.x;          // b*HH + h
    const int b = bh >> 3, h = bh & 7;
    const int t = threadIdx.x;
    __shared__ float sf[TT], sa[TT];
    const int gidx = (b * TT + t) * HH + h;
    sf[t] = gf[gidx];
    const float iv = gi[gidx];
    __syncthreads();
    #pragma unroll
    for (int st = 1; st < TT; st <<= 1) {
        float add = (t >= st) ? sf[t - st] : 0.f;
        __syncthreads();
        sf[t] += add;
        __syncthreads();
    }
    const float a = iv - sf[t];
    a_out[bh * TT + t] = a;
    sa[t] = a;
    __syncthreads();
    #pragma unroll
    for (int st = 1; st < TT; st <<= 1) {
        float mx = (t >= st) ? sa[t - st] : -3.4e38f;
        __syncthreads();
        sa[t] = fmaxf(sa[t], mx);
        __syncthreads();
    }
    M_out[bh * TT + t] = fmaxf(0.f, sa[t]);
}

// ================= parallel attention-form scan ============================
#define QT 64
#define AP 68                       // row pad (floats); 272B, 16B aligned
#define ASM_BYTES ((4*QT*AP + QT) * 4)

__global__ __launch_bounds__(256) void attn_kernel(
    const float* __restrict__ q, const float* __restrict__ kraw,
    const float* __restrict__ v, const float* __restrict__ aex,
    const float* __restrict__ Mex, const float* __restrict__ oraw,
    const float* __restrict__ skip, const float* __restrict__ rraw,
    const float* __restrict__ hlnw, const float* __restrict__ hlnb,
    fp16* __restrict__ out16)
{
    const int bh = blockIdx.y, b = bh >> 3, h = bh & 7;
    const int t0 = blockIdx.x * QT;
    extern __shared__ float sm[];
    float* ks = sm;                  // [64][AP]
    float* vs = ks + QT * AP;
    float* qs = vs + QT * AP;
    float* ss = qs + QT * AP;
    float* as_ = ss + QT * AP;       // [64]

    const int tid = threadIdx.x;
    const int qi = tid >> 2, sub = tid & 3;
    const int tq = t0 + qi;
    const size_t qbase = (size_t)(b * TT + tq) * HD + h * DH;

    {
        const int lr = tid >> 2, lc = (tid & 3) * 16;
        const float* src = q + (size_t)(b * TT + t0 + lr) * HD + h * DH + lc;
        #pragma unroll
        for (int i = 0; i < 16; i += 4)
            *(float4*)&qs[lr * AP + lc + i] = *(const float4*)(src + i);
    }
    __syncthreads();

    const float Mt = Mex[bh * TT + tq];
    float num[16];
    #pragma unroll
    for (int i = 0; i < 16; i++) num[i] = 0.f;
    float den = 0.f;

    for (int j0 = 0; j0 <= t0; j0 += QT) {
        {
            const int lr = tid >> 2, lc = (tid & 3) * 16;
            const size_t gb = (size_t)(b * TT + j0 + lr) * HD + h * DH + lc;
            #pragma unroll
            for (int i = 0; i < 16; i += 4) {
                *(float4*)&ks[lr * AP + lc + i] = *(const float4*)(kraw + gb + i);
                *(float4*)&vs[lr * AP + lc + i] = *(const float4*)(v + gb + i);
            }
            if (tid < QT) as_[tid] = aex[bh * TT + j0 + tid];
        }
        __syncthreads();

        float sc[16];
        #pragma unroll
        for (int jj = 0; jj < 16; jj++) sc[jj] = 0.f;
        const float* qrow = &qs[qi * AP];
        #pragma unroll 4
        for (int d = 0; d < DH; d += 4) {
            float q0 = qrow[d], q1 = qrow[d+1], q2 = qrow[d+2], q3 = qrow[d+3];
            #pragma unroll
            for (int jj = 0; jj < 16; jj++) {
                const float* kr = &ks[(sub + 4*jj) * AP + d];
                sc[jj] += q0*kr[0] + q1*kr[1] + q2*kr[2] + q3*kr[3];
            }
        }
        const bool diag = (j0 == t0);
        #pragma unroll
        for (int jj = 0; jj < 16; jj++) {
            const int j = sub + 4*jj;
            float w = (diag && j > qi) ? 0.f
                      : __expf(as_[j] - Mt) * 0.125f * sc[jj];
            ss[qi * AP + j] = w;
            den += w;
        }
        __syncthreads();

        #pragma unroll 8
        for (int j = 0; j < QT; j++) {
            const float s = ss[qi * AP + j];
            const float* vr = &vs[j * AP + sub];
            #pragma unroll
            for (int dd = 0; dd < 16; dd++)
                num[dd] += s * vr[4*dd];
        }
        __syncthreads();
    }

    float sumq = 0.f;
    #pragma unroll
    for (int dd = 0; dd < 16; dd++) sumq += qs[qi * AP + sub + 4*dd];
    den  += __shfl_xor_sync(0xffffffffu, den, 1);
    den  += __shfl_xor_sync(0xffffffffu, den, 2);
    sumq += __shfl_xor_sync(0xffffffffu, sumq, 1);
    sumq += __shfl_xor_sync(0xffffffffu, sumq, 2);
    den = fmaxf(den + __expf(-Mt) * sumq, 1.0f);
    const float rden = 1.f / den;

    float hh[16], s1 = 0.f, s2 = 0.f;
    #pragma unroll
    for (int dd = 0; dd < 16; dd++) {
        const int d = sub + 4*dd;
        const float ov = oraw[qbase + d];
        const float og = 1.f / (1.f + __expf(-ov));
        const float hv = og * num[dd] * rden;
        hh[dd] = hv;
        s1 += hv; s2 += hv * hv;
    }
    s1 += __shfl_xor_sync(0xffffffffu, s1, 1);
    s1 += __shfl_xor_sync(0xffffffffu, s1, 2);
    s2 += __shfl_xor_sync(0xffffffffu, s2, 1);
    s2 += __shfl_xor_sync(0xffffffffu, s2, 2);
    const float mu  = s1 * (1.f / DH);
    const float var = s2 * (1.f / DH) - mu * mu;
    const float rstd = rsqrtf(var + 1e-6f);
    #pragma unroll
    for (int dd = 0; dd < 16; dd++) {
        const int d = sub + 4*dd;
        const float hn = (hh[dd] - mu) * rstd * hlnw[h*DH + d] + hlnb[h*DH + d];
        const float rv = rraw[qbase + d];
        const float sil = rv / (1.f + __expf(-rv));
        out16[qbase + d] = __float2half((hn + skip[qbase + d]) * sil);
    }
}

// ===========================================================================
extern "C" void kernel_launch(void* const* d_in, const int* in_sizes, int n_in,
                              void* d_out, int out_size)
{
    const float* x      = (const float*)d_in[0];
    const float* ln_w   = (const float*)d_in[1];
    const float* ln_b   = (const float*)d_in[2];
    const float* hln_w  = (const float*)d_in[3];
    const float* hln_b  = (const float*)d_in[4];
    const float* Wl     = (const float*)d_in[5];
    const float* bl     = (const float*)d_in[6];
    const float* Wr     = (const float*)d_in[7];
    const float* br     = (const float*)d_in[8];
    const float* conv_w = (const float*)d_in[9];
    const float* conv_b = (const float*)d_in[10];
    const float* Wskip  = (const float*)d_in[11];
    const float* bskip  = (const float*)d_in[12];
    const float* Wi     = (const float*)d_in[13];
    const float* bi     = (const float*)d_in[14];
    const float* Wf     = (const float*)d_in[15];
    const float* bf_    = (const float*)d_in[16];
    const float* Wo     = (const float*)d_in[17];
    const float* bo     = (const float*)d_in[18];
    const float* Wq     = (const float*)d_in[19];
    const float* bq     = (const float*)d_in[20];
    const float* Wk     = (const float*)d_in[21];
    const float* bk     = (const float*)d_in[22];
    const float* Wv     = (const float*)d_in[23];
    const float* bv     = (const float*)d_in[24];
    const float* Wd     = (const float*)d_in[25];
    const float* bd     = (const float*)d_in[26];
    float* out = (float*)d_out;

    fp16 *xn16, *xt16, *xc16, *cm16;
    fp16 *WlrT, *WsT, *WqT, *WkT, *WvT, *WoT, *WdT;
    float *xt, *xc, *r, *skip, *q, *k, *v, *o, *gi, *gf, *aex, *Mex, *bias_lr;
    cudaGetSymbolAddress((void**)&xn16, g_xn16);
    cudaGetSymbolAddress((void**)&xt,   g_xt);   cudaGetSymbolAddress((void**)&xt16, g_xt16);
    cudaGetSymbolAddress((void**)&xc,   g_xc);   cudaGetSymbolAddress((void**)&xc16, g_xc16);
    cudaGetSymbolAddress((void**)&r,    g_r);    cudaGetSymbolAddress((void**)&skip, g_skip);
    cudaGetSymbolAddress((void**)&q,    g_q);    cudaGetSymbolAddress((void**)&k,    g_k);
    cudaGetSymbolAddress((void**)&v,    g_v);    cudaGetSymbolAddress((void**)&o,    g_o);
    cudaGetSymbolAddress((void**)&gi,   g_ig);   cudaGetSymbolAddress((void**)&gf,   g_fg);
    cudaGetSymbolAddress((void**)&aex,  g_a);    cudaGetSymbolAddress((void**)&Mex,  g_M);
    cudaGetSymbolAddress((void**)&cm16, g_cm16);
    cudaGetSymbolAddress((void**)&WlrT, g_WlrT);
    cudaGetSymbolAddress((void**)&WsT,  g_WsT);  cudaGetSymbolAddress((void**)&WqT,  g_WqT);
    cudaGetSymbolAddress((void**)&WkT,  g_WkT);  cudaGetSymbolAddress((void**)&WvT,  g_WvT);
    cudaGetSymbolAddress((void**)&WoT,  g_WoT);  cudaGetSymbolAddress((void**)&WdT,  g_WdT);
    cudaGetSymbolAddress((void**)&bias_lr, g_bias_lr);

    cudaFuncSetAttribute(gemm_mma_kernel,
                         cudaFuncAttributeMaxDynamicSharedMemorySize, GSMEM_BYTES);
    cudaFuncSetAttribute(attn_kernel,
                         cudaFuncAttributeMaxDynamicSharedMemorySize, ASM_BYTES);

    // 1. merged weight prep (8 transpose jobs in one launch)
    {
        PrepJobs pj{};
        const float* Ws[8] = { Wl, Wr, Wskip, Wq, Wk, Wv, Wo, Wd };
        fp16* Ts[8] = { WlrT, WlrT + (size_t)PP * DD, WsT, WqT, WkT, WvT, WoT, WdT };
        int Ks[8] = { DD, DD, PP, PP, PP, PP, PP, HD };
        int Ns[8] = { PP, HD, HD, HD, HD, HD, HD, DD };
        int cum = 0;
        for (int i = 0; i < 8; i++) {
            pj.W[i] = Ws[i]; pj.T[i] = Ts[i];
            pj.K[i] = Ks[i]; pj.N[i] = Ns[i];
            pj.cum[i] = cum;
            cum += (Ns[i] / 32) * (Ks[i] / 32);
        }
        pj.cum[8] = cum;
        prep_all_kernel<<<cum, 256>>>(pj);
    }
    bias_prep_kernel<<<10, 256>>>(bl, br);

    // 2. layernorm -> xn fp16
    ln_kernel<<<NTOK, 256>>>(x, ln_w, ln_b, xn16);

    // 3. merged [xt | r] = xn @ [Wl | Wr] + [bl | br]
    {
        GemmParams p{}; p.K = DD;
        p.jobs[0] = { xn16, WlrT, bias_lr, nullptr, xt, xt16, r, PP, PP, HD };
        gemm_mma_kernel<<<dim3(2560/128, NTOK/128, 1), 256, GSMEM_BYTES>>>(p);
    }
    // 4. conv + silu -> xc
    conv_silu_kernel<<<dim3(NTOK, PP/256), 256>>>(xt, conv_w, conv_b, xc, xc16);

    // 5. five P->HD projections in one batched launch
    {
        const int NC = 1 << 30;
        GemmParams p{}; p.K = PP;
        p.jobs[0] = { xc16, WsT, bskip, nullptr, skip, nullptr, nullptr, NC, HD, 0 };
        p.jobs[1] = { xc16, WqT, bq,    nullptr, q,    nullptr, nullptr, NC, HD, 0 };
        p.jobs[2] = { xc16, WkT, bk,    nullptr, k,    nullptr, nullptr, NC, HD, 0 };
        p.jobs[3] = { xt16, WvT, bv,    nullptr, v,    nullptr, nullptr, NC, HD, 0 };
        p.jobs[4] = { xt16, WoT, bo,    nullptr, o,    nullptr, nullptr, NC, HD, 0 };
        gemm_mma_kernel<<<dim3(HD/128, NTOK/128, 5), 256, GSMEM_BYTES>>>(p);
    }
    // 6. i/f gates (fp32) + prefix scans
    gates_kernel<<<NTOK, 256>>>(xc, Wi, bi, Wf, bf_, gi, gf);
    gatescan_kernel<<<BB*HH, TT>>>(gi, gf, aex, Mex);

    // 7. parallel attention-form scan -> comb fp16
    attn_kernel<<<dim3(TT/QT, BB*HH), 256, ASM_BYTES>>>(
        q, k, v, aex, Mex, o, skip, r, hln_w, hln_b, cm16);

    // 8. out = comb @ Wd + bd + x
    {
        const int NC = 1 << 30;
        GemmParams p{}; p.K = HD;
        p.jobs[0] = { cm16, WdT, bd, x, out, nullptr, nullptr, NC, DD, 0 };
        gemm_mma_kernel<<<dim3(DD/128, NTOK/128, 1), 256, GSMEM_BYTES>>>(p);
    }
}